// round 6
// baseline (speedup 1.0000x reference)
#include <cuda_runtime.h>
#include <cuda_bf16.h>
#include <stdint.h>
#include <math.h>

// StructureGraphMessagePassing — edge-sparse reformulation.
// GEMMs via mma.sync bf16 split-3 with PRECONVERTED hi/lo operand planes.

namespace {
constexpr int D  = 1024;
constexpr int NV = 64;
constexpr int NE = 1024;
constexpr size_t BM   = 1048576;
constexpr size_t K64  = 65536;

// fp32 scratch
constexpr size_t O_CC    = 0;
constexpr size_t O_RELJ  = 1 * BM;
constexpr size_t O_RCF   = 2 * BM;
constexpr size_t O_A0    = 3 * BM;
constexpr size_t O_B0    = O_A0 + K64;
constexpr size_t O_QS2   = O_B0 + K64;
constexpr size_t O_QO2   = O_QS2 + K64;
constexpr size_t O_VCX_A = O_QO2 + K64;
constexpr size_t O_VCX_B = O_VCX_A + K64;
constexpr size_t O_SS    = O_VCX_B + K64;
constexpr size_t O_SO    = O_SS + 1024;
constexpr size_t O_WS    = O_SS + 2048;
constexpr size_t O_WO    = O_SS + 3072;
constexpr size_t FTOTAL  = O_SS + 4096;

// bf16 hi/lo planes (lo plane at offset + size)
constexpr size_t BW_JOINT = 0;            // 4M
constexpr size_t BW_RU    = 8 * BM;       // 3M
constexpr size_t BW_SUB   = 14 * BM;      // 1M
constexpr size_t BW_OBJ   = 16 * BM;      // 1M
constexpr size_t BW_CTX   = 18 * BM;      // 3M
constexpr size_t BW_RC    = 24 * BM;      // 2M
constexpr size_t BW_NODE  = 28 * BM;      // 2M
constexpr size_t BW_FAC   = 32 * BM;      // 2M
constexpr size_t BW_W14   = 36 * BM;      // 1M
constexpr size_t BW_W24   = 38 * BM;
constexpr size_t BW_R2ST  = 40 * BM;
constexpr size_t BW_R2OT  = 42 * BM;
constexpr size_t BW_W3    = 44 * BM;
constexpr size_t BA_RVF   = 46 * BM;
constexpr size_t BA_RC0   = 48 * BM;
constexpr size_t BA_RC1   = 50 * BM;
constexpr size_t BA_RJ    = 52 * BM;
constexpr size_t BA_RELJ  = 54 * BM;
constexpr size_t BA_RTRC  = 56 * BM;
constexpr size_t BA_VJCAT = 58 * BM;                  // 256K
constexpr size_t BA_VJ    = BA_VJCAT + BM / 2;        // 64K
constexpr size_t BA_QS    = BA_VJ   + 2 * K64;
constexpr size_t BA_QO    = BA_QS   + 2 * K64;
constexpr size_t BA_CTXS  = BA_QO   + 2 * K64;
constexpr size_t BA_CTXO  = BA_CTXS + 2 * K64;
constexpr size_t BA_VCX0  = BA_CTXO + 2 * K64;
constexpr size_t BA_VCX1  = BA_VCX0 + 2 * K64;
constexpr size_t BA_VF    = BA_VCX1 + 2 * K64;
constexpr size_t BTOTAL   = BA_VF + 2 * K64;
}  // namespace

__device__ float g_buf[FTOTAL];
__device__ __nv_bfloat16 g_bf[BTOTAL];

// ---------------------------------------------------------------------------
__device__ __forceinline__ uint32_t smem_u32(const void* p) {
    uint32_t a;
    asm("{ .reg .u64 t; cvta.to.shared.u64 t, %1; cvt.u32.u64 %0, t; }"
        : "=r"(a) : "l"(p));
    return a;
}
#define LDSM4(r0, r1, r2, r3, addr) \
    asm volatile("ldmatrix.sync.aligned.m8n8.x4.shared.b16 {%0,%1,%2,%3}, [%4];" \
                 : "=r"(r0), "=r"(r1), "=r"(r2), "=r"(r3) : "r"(addr))
#define MMA16816(c, a, b0, b1) \
    asm volatile("mma.sync.aligned.m16n8k16.row.col.f32.bf16.bf16.f32 " \
                 "{%0,%1,%2,%3}, {%4,%5,%6,%7}, {%8,%9}, {%0,%1,%2,%3};" \
                 : "+f"((c)[0]), "+f"((c)[1]), "+f"((c)[2]), "+f"((c)[3]) \
                 : "r"((a)[0]), "r"((a)[1]), "r"((a)[2]), "r"((a)[3]), \
                   "r"(b0), "r"(b1))

__device__ __forceinline__ int soff(int r, int h) {
    return r * 64 + ((h ^ ((r >> 1) & 3)) << 4);
}
__device__ __forceinline__ void split1(float v, __nv_bfloat16* ph, __nv_bfloat16* pl) {
    __nv_bfloat16 h = __float2bfloat16_rn(v);
    *ph = h;
    *pl = __float2bfloat16_rn(v - __bfloat162float(h));
}

// ---------------------------------------------------------------------------
// Multi-segment multi-job NT GEMM on preconverted bf16 hi/lo planes.
// Block tile 128(M) x 64(N), K-chunks of 32, split-3, fp32 accum.
// ---------------------------------------------------------------------------
struct Seg { const __nv_bfloat16 *Ah, *Al, *Bh, *Bl; int lda, ldb, K; };
struct Job { Seg sg[3]; float* C; __nv_bfloat16 *Ch, *Cl; int ldc, nseg, mtiles, M; };
struct Batch { Job j[6]; };

__global__ __launch_bounds__(256) void tc_gemm(Batch batch) {
    const Job job = batch.j[blockIdx.z];
    if ((int)blockIdx.y >= job.mtiles) return;
    __shared__ __align__(128) char sm[2][24576];

    const int tid = threadIdx.x;
    const int wid = tid >> 5;
    const int lane = tid & 31;
    const int wm = wid >> 1;
    const int wn = wid & 1;
    const int m0 = blockIdx.y << 7;
    const int n0 = blockIdx.x << 6;
    const int rows_valid = job.M - m0;

    const int arow_l = (lane & 7) + ((lane >> 3) & 1) * 8;
    const int ah_l   = (lane >> 4) & 1;
    const int brow_l = (lane & 7) + ((lane >> 4) & 1) * 8;
    const int bh_l   = (lane >> 3) & 1;

    float c[2][4][4];
#pragma unroll
    for (int a = 0; a < 2; ++a)
#pragma unroll
        for (int b = 0; b < 4; ++b)
#pragma unroll
            for (int q = 0; q < 4; ++q) c[a][b][q] = 0.f;

    int total = 0;
#pragma unroll
    for (int s = 0; s < 3; ++s) if (s < job.nseg) total += job.sg[s].K >> 5;

    // lane mapping (A): unit = tid + i*256 -> row unit>>2, u unit&3 (64B rows, 4 units)
    const int arow0 = tid >> 2, au = tid & 3;

    // ---- fill stage 0 ----
    {
        const Seg sg = job.sg[0];
        char* dst = sm[0];
#pragma unroll
        for (int i = 0; i < 2; ++i) {
            int row = arow0 + (i << 6);
            uint4 vh = make_uint4(0, 0, 0, 0), vl = vh;
            if (row < rows_valid) {
                size_t o = (size_t)(m0 + row) * sg.lda + (au << 3);
                vh = *(const uint4*)(sg.Ah + o);
                vl = *(const uint4*)(sg.Al + o);
            }
            int off = soff(row, au);
            *(uint4*)(dst + off) = vh;
            *(uint4*)(dst + 8192 + off) = vl;
        }
        {
            size_t o = (size_t)(n0 + arow0) * sg.ldb + (au << 3);
            int off = soff(arow0, au);
            *(uint4*)(dst + 16384 + off) = *(const uint4*)(sg.Bh + o);
            *(uint4*)(dst + 20480 + off) = *(const uint4*)(sg.Bl + o);
        }
    }
    __syncthreads();

    int s = 0, ch = 0;
    for (int t = 0; t < total; ++t) {
        int s2 = s, ch2 = ch + 1;
        if (ch2 == (job.sg[s].K >> 5)) { s2 = s + 1; ch2 = 0; }
        const bool hasNext = (s2 < job.nseg);

        uint4 pah[2], pal[2], pbh, pbl;
        if (hasNext) {
            const Seg sg = job.sg[s2];
            const int k0 = ch2 << 5;
#pragma unroll
            for (int i = 0; i < 2; ++i) {
                int row = arow0 + (i << 6);
                pah[i] = make_uint4(0, 0, 0, 0); pal[i] = pah[i];
                if (row < rows_valid) {
                    size_t o = (size_t)(m0 + row) * sg.lda + k0 + (au << 3);
                    pah[i] = *(const uint4*)(sg.Ah + o);
                    pal[i] = *(const uint4*)(sg.Al + o);
                }
            }
            {
                size_t o = (size_t)(n0 + arow0) * sg.ldb + k0 + (au << 3);
                pbh = *(const uint4*)(sg.Bh + o);
                pbl = *(const uint4*)(sg.Bl + o);
            }
        }

        // ---- compute from sm[t&1] ----
        {
            const uint32_t sb = smem_u32(sm[t & 1]);
#pragma unroll
            for (int ksub = 0; ksub < 2; ++ksub) {
                const int hb = ksub << 1;
                uint32_t ah[2][4], al[2][4], bh[2][4], bl[2][4];
#pragma unroll
                for (int mi = 0; mi < 2; ++mi) {
                    int row = wm * 32 + mi * 16 + arow_l;
                    uint32_t ad = sb + soff(row, ah_l + hb);
                    LDSM4(ah[mi][0], ah[mi][1], ah[mi][2], ah[mi][3], ad);
                    LDSM4(al[mi][0], al[mi][1], al[mi][2], al[mi][3], ad + 8192);
                }
#pragma unroll
                for (int g = 0; g < 2; ++g) {
                    int row = wn * 32 + g * 16 + brow_l;
                    uint32_t bd = sb + 16384 + soff(row, bh_l + hb);
                    LDSM4(bh[g][0], bh[g][1], bh[g][2], bh[g][3], bd);
                    LDSM4(bl[g][0], bl[g][1], bl[g][2], bl[g][3], bd + 4096);
                }
#pragma unroll
                for (int mi = 0; mi < 2; ++mi)
#pragma unroll
                    for (int g = 0; g < 2; ++g)
#pragma unroll
                        for (int j = 0; j < 2; ++j) {
                            const int ni = g * 2 + j;
                            MMA16816(c[mi][ni], ah[mi], bh[g][2 * j], bh[g][2 * j + 1]);
                            MMA16816(c[mi][ni], ah[mi], bl[g][2 * j], bl[g][2 * j + 1]);
                            MMA16816(c[mi][ni], al[mi], bh[g][2 * j], bh[g][2 * j + 1]);
                        }
            }
        }

        if (hasNext) {
            char* dst = sm[(t + 1) & 1];
#pragma unroll
            for (int i = 0; i < 2; ++i) {
                int row = arow0 + (i << 6);
                int off = soff(row, au);
                *(uint4*)(dst + off) = pah[i];
                *(uint4*)(dst + 8192 + off) = pal[i];
            }
            {
                int off = soff(arow0, au);
                *(uint4*)(dst + 16384 + off) = pbh;
                *(uint4*)(dst + 20480 + off) = pbl;
            }
        }
        __syncthreads();
        s = s2; ch = ch2;
    }

    // ---- epilogue ----
    if (wm * 32 < rows_valid) {
#pragma unroll
        for (int mi = 0; mi < 2; ++mi) {
            int r0 = m0 + wm * 32 + mi * 16 + (lane >> 2);
#pragma unroll
            for (int ni = 0; ni < 4; ++ni) {
                int col = n0 + wn * 32 + ni * 8 + (lane & 3) * 2;
                float v0 = c[mi][ni][0], v1 = c[mi][ni][1];
                float v2 = c[mi][ni][2], v3 = c[mi][ni][3];
                if (job.C) {
                    *(float2*)(job.C + (size_t)r0 * job.ldc + col) = make_float2(v0, v1);
                    *(float2*)(job.C + (size_t)(r0 + 8) * job.ldc + col) = make_float2(v2, v3);
                }
                if (job.Ch) {
                    __nv_bfloat162 h0 = __floats2bfloat162_rn(v0, v1);
                    __nv_bfloat162 l0 = __floats2bfloat162_rn(v0 - __low2float(h0), v1 - __high2float(h0));
                    __nv_bfloat162 h1 = __floats2bfloat162_rn(v2, v3);
                    __nv_bfloat162 l1 = __floats2bfloat162_rn(v2 - __low2float(h1), v3 - __high2float(h1));
                    *(uint32_t*)(job.Ch + (size_t)r0 * job.ldc + col) = *(uint32_t*)&h0;
                    *(uint32_t*)(job.Cl + (size_t)r0 * job.ldc + col) = *(uint32_t*)&l0;
                    *(uint32_t*)(job.Ch + (size_t)(r0 + 8) * job.ldc + col) = *(uint32_t*)&h1;
                    *(uint32_t*)(job.Cl + (size_t)(r0 + 8) * job.ldc + col) = *(uint32_t*)&l1;
                }
            }
        }
    }
}

// ---------------------------------------------------------------------------
// Conversion of contiguous weight matrices to hi/lo planes
// ---------------------------------------------------------------------------
struct CJob { const float* s; __nv_bfloat16 *h, *l; int nblk; };
struct CJobs { CJob j[8]; };

__global__ void k_conv(CJobs js) {
    int b = blockIdx.x, ji = 0;
    while (b >= js.j[ji].nblk) { b -= js.j[ji].nblk; ++ji; }
    const CJob jb = js.j[ji];
    size_t idx = (size_t)b * 1024 + threadIdx.x * 4;
    float4 v = *(const float4*)(jb.s + idx);
    __nv_bfloat162 h0 = __floats2bfloat162_rn(v.x, v.y);
    __nv_bfloat162 h1 = __floats2bfloat162_rn(v.z, v.w);
    __nv_bfloat162 l0 = __floats2bfloat162_rn(v.x - __low2float(h0), v.y - __high2float(h0));
    __nv_bfloat162 l1 = __floats2bfloat162_rn(v.z - __low2float(h1), v.w - __high2float(h1));
    *(uint2*)(jb.h + idx) = make_uint2(*(uint32_t*)&h0, *(uint32_t*)&h1);
    *(uint2*)(jb.l + idx) = make_uint2(*(uint32_t*)&l0, *(uint32_t*)&l1);
}

// derived weights + rvf/vf planes
__global__ void k_prep(const float* __restrict__ Wrj,
                       const float* __restrict__ Wr2s,
                       const float* __restrict__ Wr2o,
                       const float* __restrict__ rvf,
                       const float* __restrict__ vf) {
    size_t idx = (size_t)blockIdx.x * blockDim.x + threadIdx.x;
    if (idx >= BM) return;
    int n = (int)(idx >> 10), k = (int)(idx & 1023);
    const float* row = Wrj + (size_t)n * 4096;
    split1(row[k] + row[3072 + k],        g_bf + BW_W14 + idx, g_bf + BW_W14 + BM + idx);
    split1(row[1024 + k] - row[3072 + k], g_bf + BW_W24 + idx, g_bf + BW_W24 + BM + idx);
    split1(row[2048 + k],                 g_bf + BW_W3  + idx, g_bf + BW_W3  + BM + idx);
    split1(Wr2s[(size_t)k * 1024 + n],    g_bf + BW_R2ST + idx, g_bf + BW_R2ST + BM + idx);
    split1(Wr2o[(size_t)k * 1024 + n],    g_bf + BW_R2OT + idx, g_bf + BW_R2OT + BM + idx);
    split1(rvf[idx],                      g_bf + BA_RVF + idx, g_bf + BA_RVF + BM + idx);
    if (idx < NV * D) {
        float v = vf[idx];
        g_buf[O_VCX_A + idx] = v;
        split1(v, g_bf + BA_VCX0 + idx, g_bf + BA_VCX0 + K64 + idx);
        split1(v, g_bf + BA_VF + idx,   g_bf + BA_VF + K64 + idx);
    }
}

// vjcat planes + rtrc planes
__global__ void k_elem1(const float* __restrict__ vf, const float* __restrict__ vcx,
                        const float* __restrict__ rvf, const float* __restrict__ rc) {
    int b = blockIdx.x;
    if (b < 256) {
        size_t idx = (size_t)b * 256 + threadIdx.x;   // 64K
        int m = (int)(idx >> 10), d = (int)(idx & 1023);
        float a = vf[idx];
        float c = vcx[idx];
        size_t o = BA_VJCAT + (size_t)m * 4096 + d;
        split1(a,     g_bf + o,        g_bf + o + BM / 4);
        split1(c,     g_bf + o + 1024, g_bf + o + BM / 4 + 1024);
        split1(a * c, g_bf + o + 2048, g_bf + o + BM / 4 + 2048);
        split1(c - a, g_bf + o + 3072, g_bf + o + BM / 4 + 3072);
    } else {
        size_t idx = (size_t)(b - 256) * 256 + threadIdx.x;  // 1M
        split1(rvf[idx] * rc[idx], g_bf + BA_RTRC + idx, g_bf + BA_RTRC + BM + idx);
    }
}

// fused rel_j build + planes + per-edge scores
__global__ void k_rs(const int* __restrict__ eidx) {
    int e = blockIdx.x, tid = threadIdx.x;
    int ei = eidx[e];
    int i = ei >> 6, j = ei & 63;
    const float* a0 = g_buf + O_A0 + ((size_t)i << 10);
    const float* b0 = g_buf + O_B0 + ((size_t)j << 10);
    const float* cc = g_buf + O_CC + ((size_t)e << 10);
    const float* qs = g_buf + O_QS2 + ((size_t)i << 10);
    const float* qo = g_buf + O_QO2 + ((size_t)j << 10);
    float s1 = 0.f, s2 = 0.f;
#pragma unroll
    for (int c = 0; c < 4; ++c) {
        int d = tid + 256 * c;
        float r = a0[d] + b0[d] + cc[d];
        size_t o = ((size_t)e << 10) + d;
        g_buf[O_RELJ + o] = r;
        split1(r, g_bf + BA_RELJ + o, g_bf + BA_RELJ + BM + o);
        s1 += qs[d] * r;
        s2 += qo[d] * r;
    }
    __shared__ float sh[2][256];
    sh[0][tid] = s1; sh[1][tid] = s2;
    __syncthreads();
    for (int st = 128; st > 0; st >>= 1) {
        if (tid < st) { sh[0][tid] += sh[0][tid + st]; sh[1][tid] += sh[1][tid + st]; }
        __syncthreads();
    }
    if (tid == 0) {
        g_buf[O_SS + e] = sh[0][0] * 0.03125f;
        g_buf[O_SO + e] = sh[1][0] * 0.03125f;
    }
}

__global__ void k_softmax(const int* __restrict__ conn) {
    int b = blockIdx.x, lane = threadIdx.x;
    bool isRow = b < 64;
    int idx = isRow ? b : b - 64;
    int e0 = isRow ? conn[idx * 64 + lane]      : conn[lane * 64 + idx];
    int e1 = isRow ? conn[idx * 64 + lane + 32] : conn[(lane + 32) * 64 + idx];
    size_t so = isRow ? O_SS : O_SO;
    float v0 = (e0 >= 0) ? g_buf[so + e0] : -1e30f;
    float v1 = (e1 >= 0) ? g_buf[so + e1] : -1e30f;
    float m = fmaxf(v0, v1);
    for (int o = 16; o > 0; o >>= 1) m = fmaxf(m, __shfl_xor_sync(0xffffffffu, m, o));
    float x0 = (e0 >= 0) ? expf(v0 - m) : 0.f;
    float x1 = (e1 >= 0) ? expf(v1 - m) : 0.f;
    float s = x0 + x1;
    for (int o = 16; o > 0; o >>= 1) s += __shfl_xor_sync(0xffffffffu, s, o);
    float inv = 1.f / s;
    size_t wo = isRow ? O_WS : O_WO;
    if (e0 >= 0) g_buf[wo + e0] = x0 * inv;
    if (e1 >= 0) g_buf[wo + e1] = x1 * inv;
}

__global__ void k_ctx(const int* __restrict__ conn) {
    int n = blockIdx.x, tid = threadIdx.x;
    float accS[4] = {0.f, 0.f, 0.f, 0.f};
    float accO[4] = {0.f, 0.f, 0.f, 0.f};
    for (int p = 0; p < 64; ++p) {
        int eS = conn[n * 64 + p];
        if (eS >= 0) {
            float w = g_buf[O_WS + eS];
            const float* r = g_buf + O_RELJ + ((size_t)eS << 10);
#pragma unroll
            for (int c = 0; c < 4; ++c) accS[c] += w * r[tid + 256 * c];
        }
        int eO = conn[p * 64 + n];
        if (eO >= 0) {
            float w = g_buf[O_WO + eO];
            const float* r = g_buf + O_RELJ + ((size_t)eO << 10);
#pragma unroll
            for (int c = 0; c < 4; ++c) accO[c] += w * r[tid + 256 * c];
        }
    }
#pragma unroll
    for (int c = 0; c < 4; ++c) {
        size_t o = ((size_t)n << 10) + tid + 256 * c;
        split1(accS[c], g_bf + BA_CTXS + o, g_bf + BA_CTXS + K64 + o);
        split1(accO[c], g_bf + BA_CTXO + o, g_bf + BA_CTXO + K64 + o);
    }
}

__global__ void k_voutepi(const int* __restrict__ conn,
                          const float* __restrict__ bnode,
                          const float* __restrict__ vf,
                          float* __restrict__ vout) {
    int i = blockIdx.x, tid = threadIdx.x;
    __shared__ int s_deg;
    if (tid == 0) {
        int dc = 0;
        for (int p = 0; p < 64; ++p)
            dc += (conn[i * 64 + p] >= 0) + (conn[p * 64 + i] >= 0);
        s_deg = dc;
    }
    __syncthreads();
    for (int d = tid; d < 1024; d += 256) {
        float v = vout[((size_t)i << 10) + d] + bnode[d];
        if (s_deg == 0) v = vf[((size_t)i << 10) + d];
        vout[((size_t)i << 10) + d] = v;
    }
}

// ---------------------------------------------------------------------------
extern "C" void kernel_launch(void* const* d_in, const int* in_sizes, int n_in,
                              void* d_out, int out_size) {
    (void)in_sizes; (void)n_in; (void)out_size;
    const float* vf     = (const float*)d_in[0];
    const float* rvf    = (const float*)d_in[1];
    const int*   conn   = (const int*)d_in[2];
    const int*   eidx   = (const int*)d_in[4];
    const float* W_sub  = (const float*)d_in[5];
    const float* W_obj  = (const float*)d_in[6];
    const float* W_joint= (const float*)d_in[9];
    const float* W_ctx  = (const float*)d_in[10];
    const float* W_ru   = (const float*)d_in[11];
    const float* W_rj   = (const float*)d_in[12];
    const float* W_rc   = (const float*)d_in[13];
    const float* W_node = (const float*)d_in[14];
    const float* b_node = (const float*)d_in[15];
    const float* W_fac  = (const float*)d_in[16];
    float* out = (float*)d_out;

    float* fb = nullptr;
    __nv_bfloat16* bb = nullptr;
    cudaGetSymbolAddress((void**)&fb, g_buf);
    cudaGetSymbolAddress((void**)&bb, g_bf);

    auto seg = [&](size_t a, size_t asz, size_t b, size_t bsz, int lda, int ldb, int K) {
        return Seg{bb + a, bb + a + asz, bb + b, bb + b + bsz, lda, ldb, K};
    };
    auto segW = [&](size_t a, size_t asz, size_t wb, size_t wsz, size_t wcol,
                    int lda, int ldb, int K) {
        return Seg{bb + a, bb + a + asz, bb + wb + wcol, bb + wb + wsz + wcol, lda, ldb, K};
    };

    // weight conversion (contiguous)
    {
        CJobs cj{};
        cj.j[0] = CJob{W_joint, bb + BW_JOINT, bb + BW_JOINT + 4 * BM, 4096};
        cj.j[1] = CJob{W_ru,    bb + BW_RU,    bb + BW_RU    + 3 * BM, 3072};
        cj.j[2] = CJob{W_sub,   bb + BW_SUB,   bb + BW_SUB   + BM,     1024};
        cj.j[3] = CJob{W_obj,   bb + BW_OBJ,   bb + BW_OBJ   + BM,     1024};
        cj.j[4] = CJob{W_ctx,   bb + BW_CTX,   bb + BW_CTX   + 3 * BM, 3072};
        cj.j[5] = CJob{W_rc,    bb + BW_RC,    bb + BW_RC    + 2 * BM, 2048};
        cj.j[6] = CJob{W_node,  bb + BW_NODE,  bb + BW_NODE  + 2 * BM, 2048};
        cj.j[7] = CJob{W_fac,   bb + BW_FAC,   bb + BW_FAC   + 2 * BM, 2048};
        k_conv<<<18432, 256>>>(cj);
    }
    k_prep<<<4096, 256>>>(W_rj, (const float*)d_in[7], (const float*)d_in[8], rvf, vf);

    for (int t = 0; t < 2; ++t) {
        const size_t rcP   = (t == 0) ? BA_RVF : BA_RC0;   // rc hi/lo planes in
        const float* rcF   = (t == 0) ? rvf : fb + O_RCF;  // rc fp32 in
        const float* vcxF  = (t == 0) ? fb + O_VCX_A : fb + O_VCX_B;
        const size_t vcxP  = (t == 0) ? BA_VCX0 : BA_VCX1;

        k_elem1<<<4352, 256>>>(vf, vcxF, rvf, rcF);

        // Launch A: vj (M=64) + rj (M=1024, 3 segs) -> planes only
        {
            Batch bt{};
            Job j0{};
            j0.sg[0] = seg(BA_VJCAT, BM / 4, BW_JOINT, 4 * BM, 4096, 4096, 4096);
            j0.nseg = 1; j0.C = nullptr; j0.Ch = bb + BA_VJ; j0.Cl = bb + BA_VJ + K64;
            j0.ldc = 1024; j0.M = 64; j0.mtiles = 1;
            bt.j[0] = j0;
            Job j1{};
            j1.sg[0] = seg(BA_RVF, BM, BW_W14, BM, 1024, 1024, 1024);
            j1.sg[1] = seg(rcP,    BM, BW_W24, BM, 1024, 1024, 1024);
            j1.sg[2] = seg(BA_RTRC, BM, BW_W3, BM, 1024, 1024, 1024);
            j1.nseg = 3; j1.C = nullptr; j1.Ch = bb + BA_RJ; j1.Cl = bb + BA_RJ + BM;
            j1.ldc = 1024; j1.M = 1024; j1.mtiles = 8;
            bt.j[1] = j1;
            tc_gemm<<<dim3(16, 8, 2), 256>>>(bt);
        }

        // Launch B: cc (f32) + A0,B0 (f32) + QS,QO (planes)
        {
            Batch bt{};
            Job j0{};
            j0.sg[0] = segW(BA_RJ, BM, BW_RU, 3 * BM, 2048, 1024, 3072, 1024);
            j0.nseg = 1; j0.C = fb + O_CC; j0.Ch = nullptr; j0.Cl = nullptr;
            j0.ldc = 1024; j0.M = 1024; j0.mtiles = 8;
            bt.j[0] = j0;
            Job j1{};
            j1.sg[0] = segW(BA_VJ, K64, BW_RU, 3 * BM, 0, 1024, 3072, 1024);
            j1.nseg = 1; j1.C = fb + O_A0; j1.ldc = 1024; j1.M = 64; j1.mtiles = 1;
            bt.j[1] = j1;
            Job j2 = j1;
            j2.sg[0] = segW(BA_VJ, K64, BW_RU, 3 * BM, 1024, 1024, 3072, 1024);
            j2.C = fb + O_B0;
            bt.j[2] = j2;
            Job j3{};
            j3.sg[0] = seg(BA_VJ, K64, BW_SUB, BM, 1024, 1024, 1024);
            j3.nseg = 1; j3.C = nullptr; j3.Ch = bb + BA_QS; j3.Cl = bb + BA_QS + K64;
            j3.ldc = 1024; j3.M = 64; j3.mtiles = 1;
            bt.j[3] = j3;
            Job j4 = j3;
            j4.sg[0] = seg(BA_VJ, K64, BW_OBJ, BM, 1024, 1024, 1024);
            j4.Ch = bb + BA_QO; j4.Cl = bb + BA_QO + K64;
            bt.j[4] = j4;
            tc_gemm<<<dim3(16, 8, 5), 256>>>(bt);
        }

        // Launch C: qs2, qo2 (f32)
        {
            Batch bt{};
            Job j0{};
            j0.sg[0] = seg(BA_QS, K64, BW_R2ST, BM, 1024, 1024, 1024);
            j0.nseg = 1; j0.C = fb + O_QS2; j0.ldc = 1024; j0.M = 64; j0.mtiles = 1;
            bt.j[0] = j0;
            Job j1 = j0;
            j1.sg[0] = seg(BA_QO, K64, BW_R2OT, BM, 1024, 1024, 1024);
            j1.C = fb + O_QO2;
            bt.j[1] = j1;
            tc_gemm<<<dim3(16, 1, 2), 256>>>(bt);
        }

        k_rs<<<1024, 256>>>(eidx);
        k_softmax<<<128, 32>>>(conn);
        k_ctx<<<64, 256>>>(conn);

        // Launch D: vctx' + rc'
        {
            Batch bt{};
            Job jv{};
            jv.sg[0] = segW(vcxP,    K64, BW_CTX, 3 * BM, 0,    1024, 3072, 1024);
            jv.sg[1] = segW(BA_CTXS, K64, BW_CTX, 3 * BM, 1024, 1024, 3072, 1024);
            jv.sg[2] = segW(BA_CTXO, K64, BW_CTX, 3 * BM, 2048, 1024, 3072, 1024);
            jv.nseg = 3; jv.ldc = 1024; jv.M = 64; jv.mtiles = 1;
            if (t == 0) {
                jv.C = fb + O_VCX_B;
                jv.Ch = bb + BA_VCX1; jv.Cl = bb + BA_VCX1 + K64;
            } else {
                jv.C = nullptr;
                jv.Ch = bb + BA_VCX0; jv.Cl = bb + BA_VCX0 + K64;
            }
            bt.j[0] = jv;
            Job jr{};
            jr.sg[0] = segW(rcP,     BM, BW_RC, 2 * BM, 0,    1024, 2048, 1024);
            jr.sg[1] = segW(BA_RELJ, BM, BW_RC, 2 * BM, 1024, 1024, 2048, 1024);
            jr.nseg = 2; jr.ldc = 1024; jr.M = 1024; jr.mtiles = 8;
            if (t == 0) {
                jr.C = fb + O_RCF;
                jr.Ch = bb + BA_RC0; jr.Cl = bb + BA_RC0 + BM;
            } else {
                jr.C = nullptr;
                jr.Ch = bb + BA_RC1; jr.Cl = bb + BA_RC1 + BM;
            }
            bt.j[1] = jr;
            tc_gemm<<<dim3(16, 8, 2), 256>>>(bt);
        }
    }

    // Final: rel_out + v_out
    float* vout = out + (size_t)NE * D;
    {
        Batch bt{};
        Job jr{};
        jr.sg[0] = segW(BA_RVF, BM, BW_FAC, 2 * BM, 0,    1024, 2048, 1024);
        jr.sg[1] = segW(BA_RC1, BM, BW_FAC, 2 * BM, 1024, 1024, 2048, 1024);
        jr.nseg = 2; jr.C = out; jr.ldc = 1024; jr.M = 1024; jr.mtiles = 8;
        bt.j[0] = jr;
        Job jv{};
        jv.sg[0] = segW(BA_VF,   K64, BW_NODE, 2 * BM, 0,    1024, 2048, 1024);
        jv.sg[1] = segW(BA_VCX0, K64, BW_NODE, 2 * BM, 1024, 1024, 2048, 1024);
        jv.nseg = 2; jv.C = vout; jv.ldc = 1024; jv.M = 64; jv.mtiles = 1;
        bt.j[1] = jv;
        tc_gemm<<<dim3(16, 8, 2), 256>>>(bt);
    }
    k_voutepi<<<64, 256>>>(conn, b_node, vf, vout);
}

// round 8
// speedup vs baseline: 1.2487x; 1.2487x over previous
#include <cuda_runtime.h>
#include <cuda_bf16.h>
#include <stdint.h>
#include <math.h>

// StructureGraphMessagePassing — edge-sparse reformulation.
// GEMMs via mma.sync bf16 split-3, preconverted hi/lo planes, cp.async pipeline.
// (R7 resubmit with static->dynamic smem fix: 96KB > 48KB static limit.)

namespace {
constexpr int D  = 1024;
constexpr int NV = 64;
constexpr int NE = 1024;
constexpr size_t BM   = 1048576;
constexpr size_t K64  = 65536;

// fp32 scratch
constexpr size_t O_CC    = 0;
constexpr size_t O_RELJ  = 1 * BM;
constexpr size_t O_RCF   = 2 * BM;
constexpr size_t O_A0    = 3 * BM;
constexpr size_t O_B0    = O_A0 + K64;
constexpr size_t O_QS2   = O_B0 + K64;
constexpr size_t O_QO2   = O_QS2 + K64;
constexpr size_t O_VCX_A = O_QO2 + K64;
constexpr size_t O_VCX_B = O_VCX_A + K64;
constexpr size_t O_SS    = O_VCX_B + K64;
constexpr size_t O_SO    = O_SS + 1024;
constexpr size_t O_WS    = O_SS + 2048;
constexpr size_t O_WO    = O_SS + 3072;
constexpr size_t FTOTAL  = O_SS + 4096;

// bf16 hi/lo planes (lo plane at offset + size)
constexpr size_t BW_JOINT = 0;
constexpr size_t BW_RU    = 8 * BM;
constexpr size_t BW_SUB   = 14 * BM;
constexpr size_t BW_OBJ   = 16 * BM;
constexpr size_t BW_CTX   = 18 * BM;
constexpr size_t BW_RC    = 24 * BM;
constexpr size_t BW_NODE  = 28 * BM;
constexpr size_t BW_FAC   = 32 * BM;
constexpr size_t BW_W14   = 36 * BM;
constexpr size_t BW_W24   = 38 * BM;
constexpr size_t BW_R2ST  = 40 * BM;
constexpr size_t BW_R2OT  = 42 * BM;
constexpr size_t BW_W3    = 44 * BM;
constexpr size_t BA_RVF   = 46 * BM;
constexpr size_t BA_RC0   = 48 * BM;
constexpr size_t BA_RC1   = 50 * BM;
constexpr size_t BA_RJ    = 52 * BM;
constexpr size_t BA_RELJ  = 54 * BM;
constexpr size_t BA_RTRC  = 56 * BM;
constexpr size_t BA_VJCAT = 58 * BM;
constexpr size_t BA_VJ    = BA_VJCAT + BM / 2;
constexpr size_t BA_QS    = BA_VJ   + 2 * K64;
constexpr size_t BA_QO    = BA_QS   + 2 * K64;
constexpr size_t BA_CTXS  = BA_QO   + 2 * K64;
constexpr size_t BA_CTXO  = BA_CTXS + 2 * K64;
constexpr size_t BA_VCX0  = BA_CTXO + 2 * K64;
constexpr size_t BA_VCX1  = BA_VCX0 + 2 * K64;
constexpr size_t BA_VF    = BA_VCX1 + 2 * K64;
constexpr size_t BTOTAL   = BA_VF + 2 * K64;

constexpr int STAGE_BYTES = 24576;
constexpr int SMEM_BYTES  = 4 * STAGE_BYTES;   // 98304
}  // namespace

__device__ float g_buf[FTOTAL];
__device__ __nv_bfloat16 g_bf[BTOTAL];

// ---------------------------------------------------------------------------
__device__ __forceinline__ uint32_t smem_u32(const void* p) {
    uint32_t a;
    asm("{ .reg .u64 t; cvta.to.shared.u64 t, %1; cvt.u32.u64 %0, t; }"
        : "=r"(a) : "l"(p));
    return a;
}
#define LDSM4(r, addr) \
    asm volatile("ldmatrix.sync.aligned.m8n8.x4.shared.b16 {%0,%1,%2,%3}, [%4];" \
                 : "=r"((r)[0]), "=r"((r)[1]), "=r"((r)[2]), "=r"((r)[3]) : "r"(addr))
#define MMA16816(c, a, b0, b1) \
    asm volatile("mma.sync.aligned.m16n8k16.row.col.f32.bf16.bf16.f32 " \
                 "{%0,%1,%2,%3}, {%4,%5,%6,%7}, {%8,%9}, {%0,%1,%2,%3};" \
                 : "+f"((c)[0]), "+f"((c)[1]), "+f"((c)[2]), "+f"((c)[3]) \
                 : "r"((a)[0]), "r"((a)[1]), "r"((a)[2]), "r"((a)[3]), \
                   "r"(b0), "r"(b1))
#define CPASYNC(dst, src, sz) \
    asm volatile("cp.async.cg.shared.global [%0], [%1], 16, %2;" \
                 :: "r"(dst), "l"(src), "r"(sz) : "memory")
#define CPCOMMIT() asm volatile("cp.async.commit_group;" ::: "memory")
#define CPWAIT2()  asm volatile("cp.async.wait_group 2;" ::: "memory")

__device__ __forceinline__ int soff(int r, int h) {
    return r * 64 + ((h ^ ((r >> 1) & 3)) << 4);
}
__device__ __forceinline__ void split1(float v, __nv_bfloat16* ph, __nv_bfloat16* pl) {
    __nv_bfloat16 h = __float2bfloat16_rn(v);
    *ph = h;
    *pl = __float2bfloat16_rn(v - __bfloat162float(h));
}

// ---------------------------------------------------------------------------
// Multi-segment multi-job NT GEMM, bf16 hi/lo planes, cp.async 4-stage pipeline.
// Block tile 128(M) x 64(N), K-chunks of 32, split-3, fp32 accum.
// ---------------------------------------------------------------------------
struct Seg { const __nv_bfloat16 *Ah, *Al, *Bh, *Bl; int lda, ldb, K; };
struct Job { Seg sg[3]; float* C; __nv_bfloat16 *Ch, *Cl; int ldc, nseg, mtiles, M; };
struct Batch { Job j[6]; };

__global__ __launch_bounds__(256, 2) void tc_gemm(Batch batch) {
    const Job job = batch.j[blockIdx.z];
    if ((int)blockIdx.y >= job.mtiles) return;
    extern __shared__ __align__(128) char sm[];

    const int tid = threadIdx.x;
    const int wid = tid >> 5;
    const int lane = tid & 31;
    const int wm = wid >> 1;
    const int wn = wid & 1;
    const int m0 = blockIdx.y << 7;
    const int n0 = blockIdx.x << 6;
    const int rows_valid = job.M - m0;

    const int arow_l = (lane & 7) + ((lane >> 3) & 1) * 8;
    const int ah_l   = (lane >> 4) & 1;
    const int brow_l = (lane & 7) + ((lane >> 4) & 1) * 8;
    const int bh_l   = (lane >> 3) & 1;

    // loader lane mapping: row = tid>>2 (0..63), unit = tid&3
    const int arow0 = tid >> 2, au = tid & 3;
    const int aoffA = soff(arow0, au);
    const int aoffA2 = soff(arow0 + 64, au);
    const uint32_t sz0 = (arow0 < rows_valid) ? 16u : 0u;
    const uint32_t sz1 = (arow0 + 64 < rows_valid) ? 16u : 0u;
    const int ar0 = (arow0 < rows_valid) ? arow0 : 0;
    const int ar1 = (arow0 + 64 < rows_valid) ? arow0 + 64 : 0;

    float c[2][4][4];
#pragma unroll
    for (int a = 0; a < 2; ++a)
#pragma unroll
        for (int b = 0; b < 4; ++b)
#pragma unroll
            for (int q = 0; q < 4; ++q) c[a][b][q] = 0.f;

    int total = 0;
#pragma unroll
    for (int s = 0; s < 3; ++s) if (s < job.nseg) total += job.sg[s].K >> 5;

    int ls = 0, lch = 0;  // load cursor
    auto issue = [&](int stage) {
        const Seg sg = job.sg[ls];
        const int k0 = lch << 5;
        const uint32_t db = smem_u32(sm + stage * STAGE_BYTES);
        {
            const __nv_bfloat16* pH = sg.Ah + (size_t)(m0 + ar0) * sg.lda + k0 + (au << 3);
            const __nv_bfloat16* pL = sg.Al + (size_t)(m0 + ar0) * sg.lda + k0 + (au << 3);
            CPASYNC(db + aoffA, pH, sz0);
            CPASYNC(db + 8192 + aoffA, pL, sz0);
        }
        {
            const __nv_bfloat16* pH = sg.Ah + (size_t)(m0 + ar1) * sg.lda + k0 + (au << 3);
            const __nv_bfloat16* pL = sg.Al + (size_t)(m0 + ar1) * sg.lda + k0 + (au << 3);
            CPASYNC(db + aoffA2, pH, sz1);
            CPASYNC(db + 8192 + aoffA2, pL, sz1);
        }
        {
            const __nv_bfloat16* pH = sg.Bh + (size_t)(n0 + arow0) * sg.ldb + k0 + (au << 3);
            const __nv_bfloat16* pL = sg.Bl + (size_t)(n0 + arow0) * sg.ldb + k0 + (au << 3);
            CPASYNC(db + 16384 + aoffA, pH, 16u);
            CPASYNC(db + 20480 + aoffA, pL, 16u);
        }
        if (++lch == (sg.K >> 5)) { lch = 0; ++ls; }
    };

    // prologue: 3 stages in flight
    issue(0); CPCOMMIT();
    issue(1); CPCOMMIT();
    issue(2); CPCOMMIT();

    for (int t = 0; t < total; ++t) {
        CPWAIT2();
        __syncthreads();

        // compute chunk t from stage t&3: load ALL fragments, then ALL MMAs
        const uint32_t sb = smem_u32(sm + (t & 3) * STAGE_BYTES);
        uint32_t fa[2][2][2][4];  // [ksub][hi/lo][mi][4]
        uint32_t fbr[2][2][2][4]; // [ksub][hi/lo][g][4]
#pragma unroll
        for (int ksub = 0; ksub < 2; ++ksub) {
            const int hb = ksub << 1;
#pragma unroll
            for (int mi = 0; mi < 2; ++mi) {
                uint32_t ad = sb + soff(wm * 32 + mi * 16 + arow_l, ah_l + hb);
                LDSM4(fa[ksub][0][mi], ad);
                LDSM4(fa[ksub][1][mi], ad + 8192);
            }
#pragma unroll
            for (int g = 0; g < 2; ++g) {
                uint32_t bd = sb + 16384 + soff(wn * 32 + g * 16 + brow_l, bh_l + hb);
                LDSM4(fbr[ksub][0][g], bd);
                LDSM4(fbr[ksub][1][g], bd + 4096);
            }
        }
#pragma unroll
        for (int ksub = 0; ksub < 2; ++ksub)
#pragma unroll
            for (int mi = 0; mi < 2; ++mi)
#pragma unroll
                for (int g = 0; g < 2; ++g)
#pragma unroll
                    for (int j = 0; j < 2; ++j) {
                        const int ni = g * 2 + j;
                        MMA16816(c[mi][ni], fa[ksub][0][mi],
                                 fbr[ksub][0][g][2 * j], fbr[ksub][0][g][2 * j + 1]);
                        MMA16816(c[mi][ni], fa[ksub][0][mi],
                                 fbr[ksub][1][g][2 * j], fbr[ksub][1][g][2 * j + 1]);
                        MMA16816(c[mi][ni], fa[ksub][1][mi],
                                 fbr[ksub][0][g][2 * j], fbr[ksub][0][g][2 * j + 1]);
                    }

        // issue chunk t+3 into stage (t+3)&3 (consumed at t-1; top-of-loop
        // barrier guarantees all warps are past reading it)
        if (t + 3 < total) issue((t + 3) & 3);
        CPCOMMIT();   // empty group when nothing issued — keeps accounting aligned
    }

    // ---- epilogue ----
    if (wm * 32 < rows_valid) {
#pragma unroll
        for (int mi = 0; mi < 2; ++mi) {
            int r0 = m0 + wm * 32 + mi * 16 + (lane >> 2);
#pragma unroll
            for (int ni = 0; ni < 4; ++ni) {
                int col = n0 + wn * 32 + ni * 8 + (lane & 3) * 2;
                float v0 = c[mi][ni][0], v1 = c[mi][ni][1];
                float v2 = c[mi][ni][2], v3 = c[mi][ni][3];
                if (job.C) {
                    *(float2*)(job.C + (size_t)r0 * job.ldc + col) = make_float2(v0, v1);
                    *(float2*)(job.C + (size_t)(r0 + 8) * job.ldc + col) = make_float2(v2, v3);
                }
                if (job.Ch) {
                    __nv_bfloat162 h0 = __floats2bfloat162_rn(v0, v1);
                    __nv_bfloat162 l0 = __floats2bfloat162_rn(v0 - __low2float(h0), v1 - __high2float(h0));
                    __nv_bfloat162 h1 = __floats2bfloat162_rn(v2, v3);
                    __nv_bfloat162 l1 = __floats2bfloat162_rn(v2 - __low2float(h1), v3 - __high2float(h1));
                    *(uint32_t*)(job.Ch + (size_t)r0 * job.ldc + col) = *(uint32_t*)&h0;
                    *(uint32_t*)(job.Cl + (size_t)r0 * job.ldc + col) = *(uint32_t*)&l0;
                    *(uint32_t*)(job.Ch + (size_t)(r0 + 8) * job.ldc + col) = *(uint32_t*)&h1;
                    *(uint32_t*)(job.Cl + (size_t)(r0 + 8) * job.ldc + col) = *(uint32_t*)&l1;
                }
            }
        }
    }
}

// ---------------------------------------------------------------------------
// Conversion kernels
// ---------------------------------------------------------------------------
struct CJob { const float* s; __nv_bfloat16 *h, *l; int nblk; };
struct CJobs { CJob j[8]; };

__global__ void k_conv(CJobs js) {
    int b = blockIdx.x, ji = 0;
    while (b >= js.j[ji].nblk) { b -= js.j[ji].nblk; ++ji; }
    const CJob jb = js.j[ji];
    size_t idx = (size_t)b * 1024 + threadIdx.x * 4;
    float4 v = *(const float4*)(jb.s + idx);
    __nv_bfloat162 h0 = __floats2bfloat162_rn(v.x, v.y);
    __nv_bfloat162 h1 = __floats2bfloat162_rn(v.z, v.w);
    __nv_bfloat162 l0 = __floats2bfloat162_rn(v.x - __low2float(h0), v.y - __high2float(h0));
    __nv_bfloat162 l1 = __floats2bfloat162_rn(v.z - __low2float(h1), v.w - __high2float(h1));
    *(uint2*)(jb.h + idx) = make_uint2(*(uint32_t*)&h0, *(uint32_t*)&h1);
    *(uint2*)(jb.l + idx) = make_uint2(*(uint32_t*)&l0, *(uint32_t*)&l1);
}

__global__ void k_prep(const float* __restrict__ Wrj,
                       const float* __restrict__ Wr2s,
                       const float* __restrict__ Wr2o,
                       const float* __restrict__ rvf,
                       const float* __restrict__ vf) {
    size_t idx = (size_t)blockIdx.x * blockDim.x + threadIdx.x;
    if (idx >= BM) return;
    int n = (int)(idx >> 10), k = (int)(idx & 1023);
    const float* row = Wrj + (size_t)n * 4096;
    split1(row[k] + row[3072 + k],        g_bf + BW_W14 + idx, g_bf + BW_W14 + BM + idx);
    split1(row[1024 + k] - row[3072 + k], g_bf + BW_W24 + idx, g_bf + BW_W24 + BM + idx);
    split1(row[2048 + k],                 g_bf + BW_W3  + idx, g_bf + BW_W3  + BM + idx);
    split1(Wr2s[(size_t)k * 1024 + n],    g_bf + BW_R2ST + idx, g_bf + BW_R2ST + BM + idx);
    split1(Wr2o[(size_t)k * 1024 + n],    g_bf + BW_R2OT + idx, g_bf + BW_R2OT + BM + idx);
    split1(rvf[idx],                      g_bf + BA_RVF + idx, g_bf + BA_RVF + BM + idx);
    if (idx < NV * D) {
        float v = vf[idx];
        g_buf[O_VCX_A + idx] = v;
        split1(v, g_bf + BA_VCX0 + idx, g_bf + BA_VCX0 + K64 + idx);
        split1(v, g_bf + BA_VF + idx,   g_bf + BA_VF + K64 + idx);
    }
}

__global__ void k_elem1(const float* __restrict__ vf, const float* __restrict__ vcx,
                        const float* __restrict__ rvf, const float* __restrict__ rc) {
    int b = blockIdx.x;
    if (b < 256) {
        size_t idx = (size_t)b * 256 + threadIdx.x;
        int m = (int)(idx >> 10), d = (int)(idx & 1023);
        float a = vf[idx];
        float c = vcx[idx];
        size_t o = BA_VJCAT + (size_t)m * 4096 + d;
        split1(a,     g_bf + o,        g_bf + o + BM / 4);
        split1(c,     g_bf + o + 1024, g_bf + o + BM / 4 + 1024);
        split1(a * c, g_bf + o + 2048, g_bf + o + BM / 4 + 2048);
        split1(c - a, g_bf + o + 3072, g_bf + o + BM / 4 + 3072);
    } else {
        size_t idx = (size_t)(b - 256) * 256 + threadIdx.x;
        split1(rvf[idx] * rc[idx], g_bf + BA_RTRC + idx, g_bf + BA_RTRC + BM + idx);
    }
}

__global__ void k_rs(const int* __restrict__ eidx) {
    int e = blockIdx.x, tid = threadIdx.x;
    int ei = eidx[e];
    int i = ei >> 6, j = ei & 63;
    const float* a0 = g_buf + O_A0 + ((size_t)i << 10);
    const float* b0 = g_buf + O_B0 + ((size_t)j << 10);
    const float* cc = g_buf + O_CC + ((size_t)e << 10);
    const float* qs = g_buf + O_QS2 + ((size_t)i << 10);
    const float* qo = g_buf + O_QO2 + ((size_t)j << 10);
    float s1 = 0.f, s2 = 0.f;
#pragma unroll
    for (int c = 0; c < 4; ++c) {
        int d = tid + 256 * c;
        float r = a0[d] + b0[d] + cc[d];
        size_t o = ((size_t)e << 10) + d;
        g_buf[O_RELJ + o] = r;
        split1(r, g_bf + BA_RELJ + o, g_bf + BA_RELJ + BM + o);
        s1 += qs[d] * r;
        s2 += qo[d] * r;
    }
    __shared__ float sh[2][256];
    sh[0][tid] = s1; sh[1][tid] = s2;
    __syncthreads();
    for (int st = 128; st > 0; st >>= 1) {
        if (tid < st) { sh[0][tid] += sh[0][tid + st]; sh[1][tid] += sh[1][tid + st]; }
        __syncthreads();
    }
    if (tid == 0) {
        g_buf[O_SS + e] = sh[0][0] * 0.03125f;
        g_buf[O_SO + e] = sh[1][0] * 0.03125f;
    }
}

__global__ void k_softmax(const int* __restrict__ conn) {
    int b = blockIdx.x, lane = threadIdx.x;
    bool isRow = b < 64;
    int idx = isRow ? b : b - 64;
    int e0 = isRow ? conn[idx * 64 + lane]      : conn[lane * 64 + idx];
    int e1 = isRow ? conn[idx * 64 + lane + 32] : conn[(lane + 32) * 64 + idx];
    size_t so = isRow ? O_SS : O_SO;
    float v0 = (e0 >= 0) ? g_buf[so + e0] : -1e30f;
    float v1 = (e1 >= 0) ? g_buf[so + e1] : -1e30f;
    float m = fmaxf(v0, v1);
    for (int o = 16; o > 0; o >>= 1) m = fmaxf(m, __shfl_xor_sync(0xffffffffu, m, o));
    float x0 = (e0 >= 0) ? expf(v0 - m) : 0.f;
    float x1 = (e1 >= 0) ? expf(v1 - m) : 0.f;
    float s = x0 + x1;
    for (int o = 16; o > 0; o >>= 1) s += __shfl_xor_sync(0xffffffffu, s, o);
    float inv = 1.f / s;
    size_t wo = isRow ? O_WS : O_WO;
    if (e0 >= 0) g_buf[wo + e0] = x0 * inv;
    if (e1 >= 0) g_buf[wo + e1] = x1 * inv;
}

__global__ void k_ctx(const int* __restrict__ conn) {
    int n = blockIdx.x, tid = threadIdx.x;
    float accS[4] = {0.f, 0.f, 0.f, 0.f};
    float accO[4] = {0.f, 0.f, 0.f, 0.f};
    for (int p = 0; p < 64; ++p) {
        int eS = conn[n * 64 + p];
        if (eS >= 0) {
            float w = g_buf[O_WS + eS];
            const float* r = g_buf + O_RELJ + ((size_t)eS << 10);
#pragma unroll
            for (int c = 0; c < 4; ++c) accS[c] += w * r[tid + 256 * c];
        }
        int eO = conn[p * 64 + n];
        if (eO >= 0) {
            float w = g_buf[O_WO + eO];
            const float* r = g_buf + O_RELJ + ((size_t)eO << 10);
#pragma unroll
            for (int c = 0; c < 4; ++c) accO[c] += w * r[tid + 256 * c];
        }
    }
#pragma unroll
    for (int c = 0; c < 4; ++c) {
        size_t o = ((size_t)n << 10) + tid + 256 * c;
        split1(accS[c], g_bf + BA_CTXS + o, g_bf + BA_CTXS + K64 + o);
        split1(accO[c], g_bf + BA_CTXO + o, g_bf + BA_CTXO + K64 + o);
    }
}

__global__ void k_voutepi(const int* __restrict__ conn,
                          const float* __restrict__ bnode,
                          const float* __restrict__ vf,
                          float* __restrict__ vout) {
    int i = blockIdx.x, tid = threadIdx.x;
    __shared__ int s_deg;
    if (tid == 0) {
        int dc = 0;
        for (int p = 0; p < 64; ++p)
            dc += (conn[i * 64 + p] >= 0) + (conn[p * 64 + i] >= 0);
        s_deg = dc;
    }
    __syncthreads();
    for (int d = tid; d < 1024; d += 256) {
        float v = vout[((size_t)i << 10) + d] + bnode[d];
        if (s_deg == 0) v = vf[((size_t)i << 10) + d];
        vout[((size_t)i << 10) + d] = v;
    }
}

// ---------------------------------------------------------------------------
extern "C" void kernel_launch(void* const* d_in, const int* in_sizes, int n_in,
                              void* d_out, int out_size) {
    (void)in_sizes; (void)n_in; (void)out_size;
    const float* vf     = (const float*)d_in[0];
    const float* rvf    = (const float*)d_in[1];
    const int*   conn   = (const int*)d_in[2];
    const int*   eidx   = (const int*)d_in[4];
    const float* W_sub  = (const float*)d_in[5];
    const float* W_obj  = (const float*)d_in[6];
    const float* W_joint= (const float*)d_in[9];
    const float* W_ctx  = (const float*)d_in[10];
    const float* W_ru   = (const float*)d_in[11];
    const float* W_rj   = (const float*)d_in[12];
    const float* W_rc   = (const float*)d_in[13];
    const float* W_node = (const float*)d_in[14];
    const float* b_node = (const float*)d_in[15];
    const float* W_fac  = (const float*)d_in[16];
    float* out = (float*)d_out;

    cudaFuncSetAttribute(tc_gemm, cudaFuncAttributeMaxDynamicSharedMemorySize, SMEM_BYTES);

    float* fb = nullptr;
    __nv_bfloat16* bb = nullptr;
    cudaGetSymbolAddress((void**)&fb, g_buf);
    cudaGetSymbolAddress((void**)&bb, g_bf);

    auto seg = [&](size_t a, size_t asz, size_t b, size_t bsz, int lda, int ldb, int K) {
        return Seg{bb + a, bb + a + asz, bb + b, bb + b + bsz, lda, ldb, K};
    };
    auto segW = [&](size_t a, size_t asz, size_t wb, size_t wsz, size_t wcol,
                    int lda, int ldb, int K) {
        return Seg{bb + a, bb + a + asz, bb + wb + wcol, bb + wb + wsz + wcol, lda, ldb, K};
    };

    {
        CJobs cj{};
        cj.j[0] = CJob{W_joint, bb + BW_JOINT, bb + BW_JOINT + 4 * BM, 4096};
        cj.j[1] = CJob{W_ru,    bb + BW_RU,    bb + BW_RU    + 3 * BM, 3072};
        cj.j[2] = CJob{W_sub,   bb + BW_SUB,   bb + BW_SUB   + BM,     1024};
        cj.j[3] = CJob{W_obj,   bb + BW_OBJ,   bb + BW_OBJ   + BM,     1024};
        cj.j[4] = CJob{W_ctx,   bb + BW_CTX,   bb + BW_CTX   + 3 * BM, 3072};
        cj.j[5] = CJob{W_rc,    bb + BW_RC,    bb + BW_RC    + 2 * BM, 2048};
        cj.j[6] = CJob{W_node,  bb + BW_NODE,  bb + BW_NODE  + 2 * BM, 2048};
        cj.j[7] = CJob{W_fac,   bb + BW_FAC,   bb + BW_FAC   + 2 * BM, 2048};
        k_conv<<<18432, 256>>>(cj);
    }
    k_prep<<<4096, 256>>>(W_rj, (const float*)d_in[7], (const float*)d_in[8], rvf, vf);

    for (int t = 0; t < 2; ++t) {
        const size_t rcP   = (t == 0) ? BA_RVF : BA_RC0;
        const float* rcF   = (t == 0) ? rvf : fb + O_RCF;
        const float* vcxF  = (t == 0) ? fb + O_VCX_A : fb + O_VCX_B;
        const size_t vcxP  = (t == 0) ? BA_VCX0 : BA_VCX1;

        k_elem1<<<4352, 256>>>(vf, vcxF, rvf, rcF);

        // Launch A: vj (M=64) + rj (M=1024, 3 segs)
        {
            Batch bt{};
            Job j0{};
            j0.sg[0] = seg(BA_VJCAT, BM / 4, BW_JOINT, 4 * BM, 4096, 4096, 4096);
            j0.nseg = 1; j0.C = nullptr; j0.Ch = bb + BA_VJ; j0.Cl = bb + BA_VJ + K64;
            j0.ldc = 1024; j0.M = 64; j0.mtiles = 1;
            bt.j[0] = j0;
            Job j1{};
            j1.sg[0] = seg(BA_RVF, BM, BW_W14, BM, 1024, 1024, 1024);
            j1.sg[1] = seg(rcP,    BM, BW_W24, BM, 1024, 1024, 1024);
            j1.sg[2] = seg(BA_RTRC, BM, BW_W3, BM, 1024, 1024, 1024);
            j1.nseg = 3; j1.C = nullptr; j1.Ch = bb + BA_RJ; j1.Cl = bb + BA_RJ + BM;
            j1.ldc = 1024; j1.M = 1024; j1.mtiles = 8;
            bt.j[1] = j1;
            tc_gemm<<<dim3(16, 8, 2), 256, SMEM_BYTES>>>(bt);
        }

        // Launch B: cc + A0,B0 + QS,QO
        {
            Batch bt{};
            Job j0{};
            j0.sg[0] = segW(BA_RJ, BM, BW_RU, 3 * BM, 2048, 1024, 3072, 1024);
            j0.nseg = 1; j0.C = fb + O_CC; j0.Ch = nullptr; j0.Cl = nullptr;
            j0.ldc = 1024; j0.M = 1024; j0.mtiles = 8;
            bt.j[0] = j0;
            Job j1{};
            j1.sg[0] = segW(BA_VJ, K64, BW_RU, 3 * BM, 0, 1024, 3072, 1024);
            j1.nseg = 1; j1.C = fb + O_A0; j1.ldc = 1024; j1.M = 64; j1.mtiles = 1;
            bt.j[1] = j1;
            Job j2 = j1;
            j2.sg[0] = segW(BA_VJ, K64, BW_RU, 3 * BM, 1024, 1024, 3072, 1024);
            j2.C = fb + O_B0;
            bt.j[2] = j2;
            Job j3{};
            j3.sg[0] = seg(BA_VJ, K64, BW_SUB, BM, 1024, 1024, 1024);
            j3.nseg = 1; j3.C = nullptr; j3.Ch = bb + BA_QS; j3.Cl = bb + BA_QS + K64;
            j3.ldc = 1024; j3.M = 64; j3.mtiles = 1;
            bt.j[3] = j3;
            Job j4 = j3;
            j4.sg[0] = seg(BA_VJ, K64, BW_OBJ, BM, 1024, 1024, 1024);
            j4.Ch = bb + BA_QO; j4.Cl = bb + BA_QO + K64;
            bt.j[4] = j4;
            tc_gemm<<<dim3(16, 8, 5), 256, SMEM_BYTES>>>(bt);
        }

        // Launch C: qs2, qo2
        {
            Batch bt{};
            Job j0{};
            j0.sg[0] = seg(BA_QS, K64, BW_R2ST, BM, 1024, 1024, 1024);
            j0.nseg = 1; j0.C = fb + O_QS2; j0.ldc = 1024; j0.M = 64; j0.mtiles = 1;
            bt.j[0] = j0;
            Job j1 = j0;
            j1.sg[0] = seg(BA_QO, K64, BW_R2OT, BM, 1024, 1024, 1024);
            j1.C = fb + O_QO2;
            bt.j[1] = j1;
            tc_gemm<<<dim3(16, 1, 2), 256, SMEM_BYTES>>>(bt);
        }

        k_rs<<<1024, 256>>>(eidx);
        k_softmax<<<128, 32>>>(conn);
        k_ctx<<<64, 256>>>(conn);

        // Launch D: vctx' + rc'
        {
            Batch bt{};
            Job jv{};
            jv.sg[0] = segW(vcxP,    K64, BW_CTX, 3 * BM, 0,    1024, 3072, 1024);
            jv.sg[1] = segW(BA_CTXS, K64, BW_CTX, 3 * BM, 1024, 1024, 3072, 1024);
            jv.sg[2] = segW(BA_CTXO, K64, BW_CTX, 3 * BM, 2048, 1024, 3072, 1024);
            jv.nseg = 3; jv.ldc = 1024; jv.M = 64; jv.mtiles = 1;
            if (t == 0) {
                jv.C = fb + O_VCX_B;
                jv.Ch = bb + BA_VCX1; jv.Cl = bb + BA_VCX1 + K64;
            } else {
                jv.C = nullptr;
                jv.Ch = bb + BA_VCX0; jv.Cl = bb + BA_VCX0 + K64;
            }
            bt.j[0] = jv;
            Job jr{};
            jr.sg[0] = segW(rcP,     BM, BW_RC, 2 * BM, 0,    1024, 2048, 1024);
            jr.sg[1] = segW(BA_RELJ, BM, BW_RC, 2 * BM, 1024, 1024, 2048, 1024);
            jr.nseg = 2; jr.ldc = 1024; jr.M = 1024; jr.mtiles = 8;
            if (t == 0) {
                jr.C = fb + O_RCF;
                jr.Ch = bb + BA_RC0; jr.Cl = bb + BA_RC0 + BM;
            } else {
                jr.C = nullptr;
                jr.Ch = bb + BA_RC1; jr.Cl = bb + BA_RC1 + BM;
            }
            bt.j[1] = jr;
            tc_gemm<<<dim3(16, 8, 2), 256, SMEM_BYTES>>>(bt);
        }
    }

    // Final: rel_out + v_out
    float* vout = out + (size_t)NE * D;
    {
        Batch bt{};
        Job jr{};
        jr.sg[0] = segW(BA_RVF, BM, BW_FAC, 2 * BM, 0,    1024, 2048, 1024);
        jr.sg[1] = segW(BA_RC1, BM, BW_FAC, 2 * BM, 1024, 1024, 2048, 1024);
        jr.nseg = 2; jr.C = out; jr.ldc = 1024; jr.M = 1024; jr.mtiles = 8;
        bt.j[0] = jr;
        Job jv{};
        jv.sg[0] = segW(BA_VF,   K64, BW_NODE, 2 * BM, 0,    1024, 2048, 1024);
        jv.sg[1] = segW(BA_VCX0, K64, BW_NODE, 2 * BM, 1024, 1024, 2048, 1024);
        jv.nseg = 2; jv.C = vout; jv.ldc = 1024; jv.M = 64; jv.mtiles = 1;
        bt.j[1] = jv;
        tc_gemm<<<dim3(16, 8, 2), 256, SMEM_BYTES>>>(bt);
    }
    k_voutepi<<<64, 256>>>(conn, b_node, vf, vout);
}

// round 9
// speedup vs baseline: 1.6029x; 1.2837x over previous
#include <cuda_runtime.h>
#include <cuda_bf16.h>
#include <stdint.h>
#include <math.h>

// StructureGraphMessagePassing — edge-sparse reformulation.
// GEMMs via mma.sync bf16 split-3, preconverted hi/lo planes, cp.async pipeline.
// R9: 64x64 block tile (128 thr, 4 warps) -> 2x CTA count, 2-3 CTAs/SM.

namespace {
constexpr int D  = 1024;
constexpr int NV = 64;
constexpr int NE = 1024;
constexpr size_t BM   = 1048576;
constexpr size_t K64  = 65536;

// fp32 scratch
constexpr size_t O_CC    = 0;
constexpr size_t O_RELJ  = 1 * BM;
constexpr size_t O_RCF   = 2 * BM;
constexpr size_t O_A0    = 3 * BM;
constexpr size_t O_B0    = O_A0 + K64;
constexpr size_t O_QS2   = O_B0 + K64;
constexpr size_t O_QO2   = O_QS2 + K64;
constexpr size_t O_VCX_A = O_QO2 + K64;
constexpr size_t O_VCX_B = O_VCX_A + K64;
constexpr size_t O_SS    = O_VCX_B + K64;
constexpr size_t O_SO    = O_SS + 1024;
constexpr size_t O_WS    = O_SS + 2048;
constexpr size_t O_WO    = O_SS + 3072;
constexpr size_t FTOTAL  = O_SS + 4096;

// bf16 hi/lo planes (lo plane at offset + size)
constexpr size_t BW_JOINT = 0;
constexpr size_t BW_RU    = 8 * BM;
constexpr size_t BW_SUB   = 14 * BM;
constexpr size_t BW_OBJ   = 16 * BM;
constexpr size_t BW_CTX   = 18 * BM;
constexpr size_t BW_RC    = 24 * BM;
constexpr size_t BW_NODE  = 28 * BM;
constexpr size_t BW_FAC   = 32 * BM;
constexpr size_t BW_W14   = 36 * BM;
constexpr size_t BW_W24   = 38 * BM;
constexpr size_t BW_R2ST  = 40 * BM;
constexpr size_t BW_R2OT  = 42 * BM;
constexpr size_t BW_W3    = 44 * BM;
constexpr size_t BA_RVF   = 46 * BM;
constexpr size_t BA_RC0   = 48 * BM;
constexpr size_t BA_RC1   = 50 * BM;
constexpr size_t BA_RJ    = 52 * BM;
constexpr size_t BA_RELJ  = 54 * BM;
constexpr size_t BA_RTRC  = 56 * BM;
constexpr size_t BA_VJCAT = 58 * BM;
constexpr size_t BA_VJ    = BA_VJCAT + BM / 2;
constexpr size_t BA_QS    = BA_VJ   + 2 * K64;
constexpr size_t BA_QO    = BA_QS   + 2 * K64;
constexpr size_t BA_CTXS  = BA_QO   + 2 * K64;
constexpr size_t BA_CTXO  = BA_CTXS + 2 * K64;
constexpr size_t BA_VCX0  = BA_CTXO + 2 * K64;
constexpr size_t BA_VCX1  = BA_VCX0 + 2 * K64;
constexpr size_t BA_VF    = BA_VCX1 + 2 * K64;
constexpr size_t BTOTAL   = BA_VF + 2 * K64;

constexpr int STAGE_BYTES = 16384;             // A hi/lo 8KB + B hi/lo 8KB
constexpr int SMEM_BYTES  = 4 * STAGE_BYTES;   // 65536
}  // namespace

__device__ float g_buf[FTOTAL];
__device__ __nv_bfloat16 g_bf[BTOTAL];

// ---------------------------------------------------------------------------
__device__ __forceinline__ uint32_t smem_u32(const void* p) {
    uint32_t a;
    asm("{ .reg .u64 t; cvta.to.shared.u64 t, %1; cvt.u32.u64 %0, t; }"
        : "=r"(a) : "l"(p));
    return a;
}
#define LDSM4(r, addr) \
    asm volatile("ldmatrix.sync.aligned.m8n8.x4.shared.b16 {%0,%1,%2,%3}, [%4];" \
                 : "=r"((r)[0]), "=r"((r)[1]), "=r"((r)[2]), "=r"((r)[3]) : "r"(addr))
#define MMA16816(c, a, b0, b1) \
    asm volatile("mma.sync.aligned.m16n8k16.row.col.f32.bf16.bf16.f32 " \
                 "{%0,%1,%2,%3}, {%4,%5,%6,%7}, {%8,%9}, {%0,%1,%2,%3};" \
                 : "+f"((c)[0]), "+f"((c)[1]), "+f"((c)[2]), "+f"((c)[3]) \
                 : "r"((a)[0]), "r"((a)[1]), "r"((a)[2]), "r"((a)[3]), \
                   "r"(b0), "r"(b1))
#define CPASYNC(dst, src, sz) \
    asm volatile("cp.async.cg.shared.global [%0], [%1], 16, %2;" \
                 :: "r"(dst), "l"(src), "r"(sz) : "memory")
#define CPCOMMIT() asm volatile("cp.async.commit_group;" ::: "memory")
#define CPWAIT2()  asm volatile("cp.async.wait_group 2;" ::: "memory")

__device__ __forceinline__ int soff(int r, int h) {
    return r * 64 + ((h ^ ((r >> 1) & 3)) << 4);
}
__device__ __forceinline__ void split1(float v, __nv_bfloat16* ph, __nv_bfloat16* pl) {
    __nv_bfloat16 h = __float2bfloat16_rn(v);
    *ph = h;
    *pl = __float2bfloat16_rn(v - __bfloat162float(h));
}

// ---------------------------------------------------------------------------
// Multi-segment multi-job NT GEMM, bf16 hi/lo planes, cp.async 4-stage pipeline.
// Block tile 64(M) x 64(N), 128 threads, K-chunks of 32, split-3, fp32 accum.
// Per-stage smem: Ahi 0 (4KB), Alo 4096, Bhi 8192, Blo 12288.
// ---------------------------------------------------------------------------
struct Seg { const __nv_bfloat16 *Ah, *Al, *Bh, *Bl; int lda, ldb, K; };
struct Job { Seg sg[3]; float* C; __nv_bfloat16 *Ch, *Cl; int ldc, nseg, mtiles, M; };
struct Batch { Job j[6]; };

__global__ __launch_bounds__(128, 3) void tc_gemm(Batch batch) {
    const Job job = batch.j[blockIdx.z];
    if ((int)blockIdx.y >= job.mtiles) return;
    extern __shared__ __align__(128) char sm[];

    const int tid = threadIdx.x;
    const int wid = tid >> 5;
    const int lane = tid & 31;
    const int wm = wid >> 1;            // 0..1
    const int wn = wid & 1;             // 0..1
    const int m0 = blockIdx.y << 6;
    const int n0 = blockIdx.x << 6;
    const int rows_valid = job.M - m0;

    const int arow_l = (lane & 7) + ((lane >> 3) & 1) * 8;
    const int ah_l   = (lane >> 4) & 1;
    const int brow_l = (lane & 7) + ((lane >> 4) & 1) * 8;
    const int bh_l   = (lane >> 3) & 1;

    // loader lane mapping: rows r0 = tid>>2 (0..31) and r0+32, unit au = tid&3
    const int r0l = tid >> 2, au = tid & 3;
    const int off0 = soff(r0l, au);
    const int off1 = soff(r0l + 32, au);
    const uint32_t sz0 = (r0l < rows_valid) ? 16u : 0u;
    const uint32_t sz1 = (r0l + 32 < rows_valid) ? 16u : 0u;
    const int ar0 = (r0l < rows_valid) ? r0l : 0;
    const int ar1 = (r0l + 32 < rows_valid) ? r0l + 32 : 0;

    float c[2][4][4];
#pragma unroll
    for (int a = 0; a < 2; ++a)
#pragma unroll
        for (int b = 0; b < 4; ++b)
#pragma unroll
            for (int q = 0; q < 4; ++q) c[a][b][q] = 0.f;

    int total = 0;
#pragma unroll
    for (int s = 0; s < 3; ++s) if (s < job.nseg) total += job.sg[s].K >> 5;

    int ls = 0, lch = 0;  // load cursor
    auto issue = [&](int stage) {
        const Seg sg = job.sg[ls];
        const int k0 = lch << 5;
        const uint32_t db = smem_u32(sm + stage * STAGE_BYTES);
        {
            size_t o0 = (size_t)(m0 + ar0) * sg.lda + k0 + (au << 3);
            size_t o1 = (size_t)(m0 + ar1) * sg.lda + k0 + (au << 3);
            CPASYNC(db + off0, sg.Ah + o0, sz0);
            CPASYNC(db + off1, sg.Ah + o1, sz1);
            CPASYNC(db + 4096 + off0, sg.Al + o0, sz0);
            CPASYNC(db + 4096 + off1, sg.Al + o1, sz1);
        }
        {
            size_t o0 = (size_t)(n0 + r0l) * sg.ldb + k0 + (au << 3);
            size_t o1 = (size_t)(n0 + r0l + 32) * sg.ldb + k0 + (au << 3);
            CPASYNC(db + 8192 + off0, sg.Bh + o0, 16u);
            CPASYNC(db + 8192 + off1, sg.Bh + o1, 16u);
            CPASYNC(db + 12288 + off0, sg.Bl + o0, 16u);
            CPASYNC(db + 12288 + off1, sg.Bl + o1, 16u);
        }
        if (++lch == (sg.K >> 5)) { lch = 0; ++ls; }
    };

    // prologue: 3 stages in flight
    issue(0); CPCOMMIT();
    issue(1); CPCOMMIT();
    issue(2); CPCOMMIT();

    for (int t = 0; t < total; ++t) {
        CPWAIT2();
        __syncthreads();

        const uint32_t sb = smem_u32(sm + (t & 3) * STAGE_BYTES);
        uint32_t fa[2][2][2][4];  // [ksub][hi/lo][mi][4]
        uint32_t fbr[2][2][2][4]; // [ksub][hi/lo][g][4]
#pragma unroll
        for (int ksub = 0; ksub < 2; ++ksub) {
            const int hb = ksub << 1;
#pragma unroll
            for (int mi = 0; mi < 2; ++mi) {
                uint32_t ad = sb + soff(wm * 32 + mi * 16 + arow_l, ah_l + hb);
                LDSM4(fa[ksub][0][mi], ad);
                LDSM4(fa[ksub][1][mi], ad + 4096);
            }
#pragma unroll
            for (int g = 0; g < 2; ++g) {
                uint32_t bd = sb + 8192 + soff(wn * 32 + g * 16 + brow_l, bh_l + hb);
                LDSM4(fbr[ksub][0][g], bd);
                LDSM4(fbr[ksub][1][g], bd + 4096);
            }
        }
#pragma unroll
        for (int ksub = 0; ksub < 2; ++ksub)
#pragma unroll
            for (int mi = 0; mi < 2; ++mi)
#pragma unroll
                for (int g = 0; g < 2; ++g)
#pragma unroll
                    for (int j = 0; j < 2; ++j) {
                        const int ni = g * 2 + j;
                        MMA16816(c[mi][ni], fa[ksub][0][mi],
                                 fbr[ksub][0][g][2 * j], fbr[ksub][0][g][2 * j + 1]);
                        MMA16816(c[mi][ni], fa[ksub][0][mi],
                                 fbr[ksub][1][g][2 * j], fbr[ksub][1][g][2 * j + 1]);
                        MMA16816(c[mi][ni], fa[ksub][1][mi],
                                 fbr[ksub][0][g][2 * j], fbr[ksub][0][g][2 * j + 1]);
                    }

        if (t + 3 < total) issue((t + 3) & 3);
        CPCOMMIT();   // empty group when nothing issued — keeps accounting aligned
    }

    // ---- epilogue ----
    if (wm * 32 < rows_valid) {
#pragma unroll
        for (int mi = 0; mi < 2; ++mi) {
            int r0 = m0 + wm * 32 + mi * 16 + (lane >> 2);
#pragma unroll
            for (int ni = 0; ni < 4; ++ni) {
                int col = n0 + wn * 32 + ni * 8 + (lane & 3) * 2;
                float v0 = c[mi][ni][0], v1 = c[mi][ni][1];
                float v2 = c[mi][ni][2], v3 = c[mi][ni][3];
                if (job.C) {
                    *(float2*)(job.C + (size_t)r0 * job.ldc + col) = make_float2(v0, v1);
                    *(float2*)(job.C + (size_t)(r0 + 8) * job.ldc + col) = make_float2(v2, v3);
                }
                if (job.Ch) {
                    __nv_bfloat162 h0 = __floats2bfloat162_rn(v0, v1);
                    __nv_bfloat162 l0 = __floats2bfloat162_rn(v0 - __low2float(h0), v1 - __high2float(h0));
                    __nv_bfloat162 h1 = __floats2bfloat162_rn(v2, v3);
                    __nv_bfloat162 l1 = __floats2bfloat162_rn(v2 - __low2float(h1), v3 - __high2float(h1));
                    *(uint32_t*)(job.Ch + (size_t)r0 * job.ldc + col) = *(uint32_t*)&h0;
                    *(uint32_t*)(job.Cl + (size_t)r0 * job.ldc + col) = *(uint32_t*)&l0;
                    *(uint32_t*)(job.Ch + (size_t)(r0 + 8) * job.ldc + col) = *(uint32_t*)&h1;
                    *(uint32_t*)(job.Cl + (size_t)(r0 + 8) * job.ldc + col) = *(uint32_t*)&l1;
                }
            }
        }
    }
}

// ---------------------------------------------------------------------------
// Conversion kernels
// ---------------------------------------------------------------------------
struct CJob { const float* s; __nv_bfloat16 *h, *l; int nblk; };
struct CJobs { CJob j[8]; };

__global__ void k_conv(CJobs js) {
    int b = blockIdx.x, ji = 0;
    while (b >= js.j[ji].nblk) { b -= js.j[ji].nblk; ++ji; }
    const CJob jb = js.j[ji];
    size_t idx = (size_t)b * 1024 + threadIdx.x * 4;
    float4 v = *(const float4*)(jb.s + idx);
    __nv_bfloat162 h0 = __floats2bfloat162_rn(v.x, v.y);
    __nv_bfloat162 h1 = __floats2bfloat162_rn(v.z, v.w);
    __nv_bfloat162 l0 = __floats2bfloat162_rn(v.x - __low2float(h0), v.y - __high2float(h0));
    __nv_bfloat162 l1 = __floats2bfloat162_rn(v.z - __low2float(h1), v.w - __high2float(h1));
    *(uint2*)(jb.h + idx) = make_uint2(*(uint32_t*)&h0, *(uint32_t*)&h1);
    *(uint2*)(jb.l + idx) = make_uint2(*(uint32_t*)&l0, *(uint32_t*)&l1);
}

__global__ void k_prep(const float* __restrict__ Wrj,
                       const float* __restrict__ Wr2s,
                       const float* __restrict__ Wr2o,
                       const float* __restrict__ rvf,
                       const float* __restrict__ vf) {
    size_t idx = (size_t)blockIdx.x * blockDim.x + threadIdx.x;
    if (idx >= BM) return;
    int n = (int)(idx >> 10), k = (int)(idx & 1023);
    const float* row = Wrj + (size_t)n * 4096;
    split1(row[k] + row[3072 + k],        g_bf + BW_W14 + idx, g_bf + BW_W14 + BM + idx);
    split1(row[1024 + k] - row[3072 + k], g_bf + BW_W24 + idx, g_bf + BW_W24 + BM + idx);
    split1(row[2048 + k],                 g_bf + BW_W3  + idx, g_bf + BW_W3  + BM + idx);
    split1(Wr2s[(size_t)k * 1024 + n],    g_bf + BW_R2ST + idx, g_bf + BW_R2ST + BM + idx);
    split1(Wr2o[(size_t)k * 1024 + n],    g_bf + BW_R2OT + idx, g_bf + BW_R2OT + BM + idx);
    split1(rvf[idx],                      g_bf + BA_RVF + idx, g_bf + BA_RVF + BM + idx);
    if (idx < NV * D) {
        float v = vf[idx];
        g_buf[O_VCX_A + idx] = v;
        split1(v, g_bf + BA_VCX0 + idx, g_bf + BA_VCX0 + K64 + idx);
        split1(v, g_bf + BA_VF + idx,   g_bf + BA_VF + K64 + idx);
    }
}

__global__ void k_elem1(const float* __restrict__ vf, const float* __restrict__ vcx,
                        const float* __restrict__ rvf, const float* __restrict__ rc) {
    int b = blockIdx.x;
    if (b < 256) {
        size_t idx = (size_t)b * 256 + threadIdx.x;
        int m = (int)(idx >> 10), d = (int)(idx & 1023);
        float a = vf[idx];
        float c = vcx[idx];
        size_t o = BA_VJCAT + (size_t)m * 4096 + d;
        split1(a,     g_bf + o,        g_bf + o + BM / 4);
        split1(c,     g_bf + o + 1024, g_bf + o + BM / 4 + 1024);
        split1(a * c, g_bf + o + 2048, g_bf + o + BM / 4 + 2048);
        split1(c - a, g_bf + o + 3072, g_bf + o + BM / 4 + 3072);
    } else {
        size_t idx = (size_t)(b - 256) * 256 + threadIdx.x;
        split1(rvf[idx] * rc[idx], g_bf + BA_RTRC + idx, g_bf + BA_RTRC + BM + idx);
    }
}

__global__ void k_rs(const int* __restrict__ eidx) {
    int e = blockIdx.x, tid = threadIdx.x;
    int ei = eidx[e];
    int i = ei >> 6, j = ei & 63;
    const float* a0 = g_buf + O_A0 + ((size_t)i << 10);
    const float* b0 = g_buf + O_B0 + ((size_t)j << 10);
    const float* cc = g_buf + O_CC + ((size_t)e << 10);
    const float* qs = g_buf + O_QS2 + ((size_t)i << 10);
    const float* qo = g_buf + O_QO2 + ((size_t)j << 10);
    float s1 = 0.f, s2 = 0.f;
#pragma unroll
    for (int c = 0; c < 4; ++c) {
        int d = tid + 256 * c;
        float r = a0[d] + b0[d] + cc[d];
        size_t o = ((size_t)e << 10) + d;
        g_buf[O_RELJ + o] = r;
        split1(r, g_bf + BA_RELJ + o, g_bf + BA_RELJ + BM + o);
        s1 += qs[d] * r;
        s2 += qo[d] * r;
    }
    __shared__ float sh[2][256];
    sh[0][tid] = s1; sh[1][tid] = s2;
    __syncthreads();
    for (int st = 128; st > 0; st >>= 1) {
        if (tid < st) { sh[0][tid] += sh[0][tid + st]; sh[1][tid] += sh[1][tid + st]; }
        __syncthreads();
    }
    if (tid == 0) {
        g_buf[O_SS + e] = sh[0][0] * 0.03125f;
        g_buf[O_SO + e] = sh[1][0] * 0.03125f;
    }
}

__global__ void k_softmax(const int* __restrict__ conn) {
    int b = blockIdx.x, lane = threadIdx.x;
    bool isRow = b < 64;
    int idx = isRow ? b : b - 64;
    int e0 = isRow ? conn[idx * 64 + lane]      : conn[lane * 64 + idx];
    int e1 = isRow ? conn[idx * 64 + lane + 32] : conn[(lane + 32) * 64 + idx];
    size_t so = isRow ? O_SS : O_SO;
    float v0 = (e0 >= 0) ? g_buf[so + e0] : -1e30f;
    float v1 = (e1 >= 0) ? g_buf[so + e1] : -1e30f;
    float m = fmaxf(v0, v1);
    for (int o = 16; o > 0; o >>= 1) m = fmaxf(m, __shfl_xor_sync(0xffffffffu, m, o));
    float x0 = (e0 >= 0) ? expf(v0 - m) : 0.f;
    float x1 = (e1 >= 0) ? expf(v1 - m) : 0.f;
    float s = x0 + x1;
    for (int o = 16; o > 0; o >>= 1) s += __shfl_xor_sync(0xffffffffu, s, o);
    float inv = 1.f / s;
    size_t wo = isRow ? O_WS : O_WO;
    if (e0 >= 0) g_buf[wo + e0] = x0 * inv;
    if (e1 >= 0) g_buf[wo + e1] = x1 * inv;
}

__global__ void k_ctx(const int* __restrict__ conn) {
    int n = blockIdx.x, tid = threadIdx.x;
    float accS[4] = {0.f, 0.f, 0.f, 0.f};
    float accO[4] = {0.f, 0.f, 0.f, 0.f};
    for (int p = 0; p < 64; ++p) {
        int eS = conn[n * 64 + p];
        if (eS >= 0) {
            float w = g_buf[O_WS + eS];
            const float* r = g_buf + O_RELJ + ((size_t)eS << 10);
#pragma unroll
            for (int c = 0; c < 4; ++c) accS[c] += w * r[tid + 256 * c];
        }
        int eO = conn[p * 64 + n];
        if (eO >= 0) {
            float w = g_buf[O_WO + eO];
            const float* r = g_buf + O_RELJ + ((size_t)eO << 10);
#pragma unroll
            for (int c = 0; c < 4; ++c) accO[c] += w * r[tid + 256 * c];
        }
    }
#pragma unroll
    for (int c = 0; c < 4; ++c) {
        size_t o = ((size_t)n << 10) + tid + 256 * c;
        split1(accS[c], g_bf + BA_CTXS + o, g_bf + BA_CTXS + K64 + o);
        split1(accO[c], g_bf + BA_CTXO + o, g_bf + BA_CTXO + K64 + o);
    }
}

__global__ void k_voutepi(const int* __restrict__ conn,
                          const float* __restrict__ bnode,
                          const float* __restrict__ vf,
                          float* __restrict__ vout) {
    int i = blockIdx.x, tid = threadIdx.x;
    __shared__ int s_deg;
    if (tid == 0) {
        int dc = 0;
        for (int p = 0; p < 64; ++p)
            dc += (conn[i * 64 + p] >= 0) + (conn[p * 64 + i] >= 0);
        s_deg = dc;
    }
    __syncthreads();
    for (int d = tid; d < 1024; d += 256) {
        float v = vout[((size_t)i << 10) + d] + bnode[d];
        if (s_deg == 0) v = vf[((size_t)i << 10) + d];
        vout[((size_t)i << 10) + d] = v;
    }
}

// ---------------------------------------------------------------------------
extern "C" void kernel_launch(void* const* d_in, const int* in_sizes, int n_in,
                              void* d_out, int out_size) {
    (void)in_sizes; (void)n_in; (void)out_size;
    const float* vf     = (const float*)d_in[0];
    const float* rvf    = (const float*)d_in[1];
    const int*   conn   = (const int*)d_in[2];
    const int*   eidx   = (const int*)d_in[4];
    const float* W_sub  = (const float*)d_in[5];
    const float* W_obj  = (const float*)d_in[6];
    const float* W_joint= (const float*)d_in[9];
    const float* W_ctx  = (const float*)d_in[10];
    const float* W_ru   = (const float*)d_in[11];
    const float* W_rj   = (const float*)d_in[12];
    const float* W_rc   = (const float*)d_in[13];
    const float* W_node = (const float*)d_in[14];
    const float* b_node = (const float*)d_in[15];
    const float* W_fac  = (const float*)d_in[16];
    float* out = (float*)d_out;

    cudaFuncSetAttribute(tc_gemm, cudaFuncAttributeMaxDynamicSharedMemorySize, SMEM_BYTES);

    float* fb = nullptr;
    __nv_bfloat16* bb = nullptr;
    cudaGetSymbolAddress((void**)&fb, g_buf);
    cudaGetSymbolAddress((void**)&bb, g_bf);

    auto seg = [&](size_t a, size_t asz, size_t b, size_t bsz, int lda, int ldb, int K) {
        return Seg{bb + a, bb + a + asz, bb + b, bb + b + bsz, lda, ldb, K};
    };
    auto segW = [&](size_t a, size_t asz, size_t wb, size_t wsz, size_t wcol,
                    int lda, int ldb, int K) {
        return Seg{bb + a, bb + a + asz, bb + wb + wcol, bb + wb + wsz + wcol, lda, ldb, K};
    };

    {
        CJobs cj{};
        cj.j[0] = CJob{W_joint, bb + BW_JOINT, bb + BW_JOINT + 4 * BM, 4096};
        cj.j[1] = CJob{W_ru,    bb + BW_RU,    bb + BW_RU    + 3 * BM, 3072};
        cj.j[2] = CJob{W_sub,   bb + BW_SUB,   bb + BW_SUB   + BM,     1024};
        cj.j[3] = CJob{W_obj,   bb + BW_OBJ,   bb + BW_OBJ   + BM,     1024};
        cj.j[4] = CJob{W_ctx,   bb + BW_CTX,   bb + BW_CTX   + 3 * BM, 3072};
        cj.j[5] = CJob{W_rc,    bb + BW_RC,    bb + BW_RC    + 2 * BM, 2048};
        cj.j[6] = CJob{W_node,  bb + BW_NODE,  bb + BW_NODE  + 2 * BM, 2048};
        cj.j[7] = CJob{W_fac,   bb + BW_FAC,   bb + BW_FAC   + 2 * BM, 2048};
        k_conv<<<18432, 256>>>(cj);
    }
    k_prep<<<4096, 256>>>(W_rj, (const float*)d_in[7], (const float*)d_in[8], rvf, vf);

    for (int t = 0; t < 2; ++t) {
        const size_t rcP   = (t == 0) ? BA_RVF : BA_RC0;
        const float* rcF   = (t == 0) ? rvf : fb + O_RCF;
        const float* vcxF  = (t == 0) ? fb + O_VCX_A : fb + O_VCX_B;
        const size_t vcxP  = (t == 0) ? BA_VCX0 : BA_VCX1;

        k_elem1<<<4352, 256>>>(vf, vcxF, rvf, rcF);

        // Launch A: vj (M=64) + rj (M=1024, 3 segs)
        {
            Batch bt{};
            Job j0{};
            j0.sg[0] = seg(BA_VJCAT, BM / 4, BW_JOINT, 4 * BM, 4096, 4096, 4096);
            j0.nseg = 1; j0.C = nullptr; j0.Ch = bb + BA_VJ; j0.Cl = bb + BA_VJ + K64;
            j0.ldc = 1024; j0.M = 64; j0.mtiles = 1;
            bt.j[0] = j0;
            Job j1{};
            j1.sg[0] = seg(BA_RVF, BM, BW_W14, BM, 1024, 1024, 1024);
            j1.sg[1] = seg(rcP,    BM, BW_W24, BM, 1024, 1024, 1024);
            j1.sg[2] = seg(BA_RTRC, BM, BW_W3, BM, 1024, 1024, 1024);
            j1.nseg = 3; j1.C = nullptr; j1.Ch = bb + BA_RJ; j1.Cl = bb + BA_RJ + BM;
            j1.ldc = 1024; j1.M = 1024; j1.mtiles = 16;
            bt.j[1] = j1;
            tc_gemm<<<dim3(16, 16, 2), 128, SMEM_BYTES>>>(bt);
        }

        // Launch B: cc + A0,B0 + QS,QO
        {
            Batch bt{};
            Job j0{};
            j0.sg[0] = segW(BA_RJ, BM, BW_RU, 3 * BM, 2048, 1024, 3072, 1024);
            j0.nseg = 1; j0.C = fb + O_CC; j0.Ch = nullptr; j0.Cl = nullptr;
            j0.ldc = 1024; j0.M = 1024; j0.mtiles = 16;
            bt.j[0] = j0;
            Job j1{};
            j1.sg[0] = segW(BA_VJ, K64, BW_RU, 3 * BM, 0, 1024, 3072, 1024);
            j1.nseg = 1; j1.C = fb + O_A0; j1.ldc = 1024; j1.M = 64; j1.mtiles = 1;
            bt.j[1] = j1;
            Job j2 = j1;
            j2.sg[0] = segW(BA_VJ, K64, BW_RU, 3 * BM, 1024, 1024, 3072, 1024);
            j2.C = fb + O_B0;
            bt.j[2] = j2;
            Job j3{};
            j3.sg[0] = seg(BA_VJ, K64, BW_SUB, BM, 1024, 1024, 1024);
            j3.nseg = 1; j3.C = nullptr; j3.Ch = bb + BA_QS; j3.Cl = bb + BA_QS + K64;
            j3.ldc = 1024; j3.M = 64; j3.mtiles = 1;
            bt.j[3] = j3;
            Job j4 = j3;
            j4.sg[0] = seg(BA_VJ, K64, BW_OBJ, BM, 1024, 1024, 1024);
            j4.Ch = bb + BA_QO; j4.Cl = bb + BA_QO + K64;
            bt.j[4] = j4;
            tc_gemm<<<dim3(16, 16, 5), 128, SMEM_BYTES>>>(bt);
        }

        // Launch C: qs2, qo2
        {
            Batch bt{};
            Job j0{};
            j0.sg[0] = seg(BA_QS, K64, BW_R2ST, BM, 1024, 1024, 1024);
            j0.nseg = 1; j0.C = fb + O_QS2; j0.ldc = 1024; j0.M = 64; j0.mtiles = 1;
            bt.j[0] = j0;
            Job j1 = j0;
            j1.sg[0] = seg(BA_QO, K64, BW_R2OT, BM, 1024, 1024, 1024);
            j1.C = fb + O_QO2;
            bt.j[1] = j1;
            tc_gemm<<<dim3(16, 1, 2), 128, SMEM_BYTES>>>(bt);
        }

        k_rs<<<1024, 256>>>(eidx);
        k_softmax<<<128, 32>>>(conn);
        k_ctx<<<64, 256>>>(conn);

        // Launch D: vctx' + rc'
        {
            Batch bt{};
            Job jv{};
            jv.sg[0] = segW(vcxP,    K64, BW_CTX, 3 * BM, 0,    1024, 3072, 1024);
            jv.sg[1] = segW(BA_CTXS, K64, BW_CTX, 3 * BM, 1024, 1024, 3072, 1024);
            jv.sg[2] = segW(BA_CTXO, K64, BW_CTX, 3 * BM, 2048, 1024, 3072, 1024);
            jv.nseg = 3; jv.ldc = 1024; jv.M = 64; jv.mtiles = 1;
            if (t == 0) {
                jv.C = fb + O_VCX_B;
                jv.Ch = bb + BA_VCX1; jv.Cl = bb + BA_VCX1 + K64;
            } else {
                jv.C = nullptr;
                jv.Ch = bb + BA_VCX0; jv.Cl = bb + BA_VCX0 + K64;
            }
            bt.j[0] = jv;
            Job jr{};
            jr.sg[0] = segW(rcP,     BM, BW_RC, 2 * BM, 0,    1024, 2048, 1024);
            jr.sg[1] = segW(BA_RELJ, BM, BW_RC, 2 * BM, 1024, 1024, 2048, 1024);
            jr.nseg = 2; jr.ldc = 1024; jr.M = 1024; jr.mtiles = 16;
            if (t == 0) {
                jr.C = fb + O_RCF;
                jr.Ch = bb + BA_RC0; jr.Cl = bb + BA_RC0 + BM;
            } else {
                jr.C = nullptr;
                jr.Ch = bb + BA_RC1; jr.Cl = bb + BA_RC1 + BM;
            }
            bt.j[1] = jr;
            tc_gemm<<<dim3(16, 16, 2), 128, SMEM_BYTES>>>(bt);
        }
    }

    // Final: rel_out + v_out
    float* vout = out + (size_t)NE * D;
    {
        Batch bt{};
        Job jr{};
        jr.sg[0] = segW(BA_RVF, BM, BW_FAC, 2 * BM, 0,    1024, 2048, 1024);
        jr.sg[1] = segW(BA_RC1, BM, BW_FAC, 2 * BM, 1024, 1024, 2048, 1024);
        jr.nseg = 2; jr.C = out; jr.ldc = 1024; jr.M = 1024; jr.mtiles = 16;
        bt.j[0] = jr;
        Job jv{};
        jv.sg[0] = segW(BA_VF,   K64, BW_NODE, 2 * BM, 0,    1024, 2048, 1024);
        jv.sg[1] = segW(BA_VCX0, K64, BW_NODE, 2 * BM, 1024, 1024, 2048, 1024);
        jv.nseg = 2; jv.C = vout; jv.ldc = 1024; jv.M = 64; jv.mtiles = 1;
        bt.j[1] = jv;
        tc_gemm<<<dim3(16, 16, 2), 128, SMEM_BYTES>>>(bt);
    }
    k_voutepi<<<64, 256>>>(conn, b_node, vf, vout);
}

// round 10
// speedup vs baseline: 1.7975x; 1.1214x over previous
#include <cuda_runtime.h>
#include <cuda_bf16.h>
#include <stdint.h>
#include <math.h>

// StructureGraphMessagePassing — edge-sparse reformulation.
// GEMMs via mma.sync bf16 split-3, preconverted hi/lo planes.
// R10: 6-stage cp.async pipeline (prefetch distance 5 chunks).

namespace {
constexpr int D  = 1024;
constexpr int NV = 64;
constexpr int NE = 1024;
constexpr size_t BM   = 1048576;
constexpr size_t K64  = 65536;

// fp32 scratch
constexpr size_t O_CC    = 0;
constexpr size_t O_RELJ  = 1 * BM;
constexpr size_t O_RCF   = 2 * BM;
constexpr size_t O_A0    = 3 * BM;
constexpr size_t O_B0    = O_A0 + K64;
constexpr size_t O_QS2   = O_B0 + K64;
constexpr size_t O_QO2   = O_QS2 + K64;
constexpr size_t O_VCX_A = O_QO2 + K64;
constexpr size_t O_VCX_B = O_VCX_A + K64;
constexpr size_t O_SS    = O_VCX_B + K64;
constexpr size_t O_SO    = O_SS + 1024;
constexpr size_t O_WS    = O_SS + 2048;
constexpr size_t O_WO    = O_SS + 3072;
constexpr size_t FTOTAL  = O_SS + 4096;

// bf16 hi/lo planes (lo plane at offset + size)
constexpr size_t BW_JOINT = 0;
constexpr size_t BW_RU    = 8 * BM;
constexpr size_t BW_SUB   = 14 * BM;
constexpr size_t BW_OBJ   = 16 * BM;
constexpr size_t BW_CTX   = 18 * BM;
constexpr size_t BW_RC    = 24 * BM;
constexpr size_t BW_NODE  = 28 * BM;
constexpr size_t BW_FAC   = 32 * BM;
constexpr size_t BW_W14   = 36 * BM;
constexpr size_t BW_W24   = 38 * BM;
constexpr size_t BW_R2ST  = 40 * BM;
constexpr size_t BW_R2OT  = 42 * BM;
constexpr size_t BW_W3    = 44 * BM;
constexpr size_t BA_RVF   = 46 * BM;
constexpr size_t BA_RC0   = 48 * BM;
constexpr size_t BA_RC1   = 50 * BM;
constexpr size_t BA_RJ    = 52 * BM;
constexpr size_t BA_RELJ  = 54 * BM;
constexpr size_t BA_RTRC  = 56 * BM;
constexpr size_t BA_VJCAT = 58 * BM;
constexpr size_t BA_VJ    = BA_VJCAT + BM / 2;
constexpr size_t BA_QS    = BA_VJ   + 2 * K64;
constexpr size_t BA_QO    = BA_QS   + 2 * K64;
constexpr size_t BA_CTXS  = BA_QO   + 2 * K64;
constexpr size_t BA_CTXO  = BA_CTXS + 2 * K64;
constexpr size_t BA_VCX0  = BA_CTXO + 2 * K64;
constexpr size_t BA_VCX1  = BA_VCX0 + 2 * K64;
constexpr size_t BA_VF    = BA_VCX1 + 2 * K64;
constexpr size_t BTOTAL   = BA_VF + 2 * K64;

constexpr int STAGE_BYTES = 16384;             // A hi/lo 8KB + B hi/lo 8KB
constexpr int NSTAGE      = 6;
constexpr int SMEM_BYTES  = NSTAGE * STAGE_BYTES;   // 98304
}  // namespace

__device__ float g_buf[FTOTAL];
__device__ __nv_bfloat16 g_bf[BTOTAL];

// ---------------------------------------------------------------------------
__device__ __forceinline__ uint32_t smem_u32(const void* p) {
    uint32_t a;
    asm("{ .reg .u64 t; cvta.to.shared.u64 t, %1; cvt.u32.u64 %0, t; }"
        : "=r"(a) : "l"(p));
    return a;
}
#define LDSM4(r, addr) \
    asm volatile("ldmatrix.sync.aligned.m8n8.x4.shared.b16 {%0,%1,%2,%3}, [%4];" \
                 : "=r"((r)[0]), "=r"((r)[1]), "=r"((r)[2]), "=r"((r)[3]) : "r"(addr))
#define MMA16816(c, a, b0, b1) \
    asm volatile("mma.sync.aligned.m16n8k16.row.col.f32.bf16.bf16.f32 " \
                 "{%0,%1,%2,%3}, {%4,%5,%6,%7}, {%8,%9}, {%0,%1,%2,%3};" \
                 : "+f"((c)[0]), "+f"((c)[1]), "+f"((c)[2]), "+f"((c)[3]) \
                 : "r"((a)[0]), "r"((a)[1]), "r"((a)[2]), "r"((a)[3]), \
                   "r"(b0), "r"(b1))
#define CPASYNC(dst, src, sz) \
    asm volatile("cp.async.cg.shared.global [%0], [%1], 16, %2;" \
                 :: "r"(dst), "l"(src), "r"(sz) : "memory")
#define CPCOMMIT() asm volatile("cp.async.commit_group;" ::: "memory")
#define CPWAIT4()  asm volatile("cp.async.wait_group 4;" ::: "memory")

__device__ __forceinline__ int soff(int r, int h) {
    return r * 64 + ((h ^ ((r >> 1) & 3)) << 4);
}
__device__ __forceinline__ void split1(float v, __nv_bfloat16* ph, __nv_bfloat16* pl) {
    __nv_bfloat16 h = __float2bfloat16_rn(v);
    *ph = h;
    *pl = __float2bfloat16_rn(v - __bfloat162float(h));
}

// ---------------------------------------------------------------------------
// Multi-segment multi-job NT GEMM, bf16 hi/lo planes, cp.async 6-stage pipeline.
// Block tile 64(M) x 64(N), 128 threads, K-chunks of 32, split-3, fp32 accum.
// Per-stage smem: Ahi 0 (4KB), Alo 4096, Bhi 8192, Blo 12288.
// ---------------------------------------------------------------------------
struct Seg { const __nv_bfloat16 *Ah, *Al, *Bh, *Bl; int lda, ldb, K; };
struct Job { Seg sg[3]; float* C; __nv_bfloat16 *Ch, *Cl; int ldc, nseg, mtiles, M; };
struct Batch { Job j[6]; };

__global__ __launch_bounds__(128, 2) void tc_gemm(Batch batch) {
    const Job job = batch.j[blockIdx.z];
    if ((int)blockIdx.y >= job.mtiles) return;
    extern __shared__ __align__(128) char sm[];

    const int tid = threadIdx.x;
    const int wid = tid >> 5;
    const int lane = tid & 31;
    const int wm = wid >> 1;            // 0..1
    const int wn = wid & 1;             // 0..1
    const int m0 = blockIdx.y << 6;
    const int n0 = blockIdx.x << 6;
    const int rows_valid = job.M - m0;

    const int arow_l = (lane & 7) + ((lane >> 3) & 1) * 8;
    const int ah_l   = (lane >> 4) & 1;
    const int brow_l = (lane & 7) + ((lane >> 4) & 1) * 8;
    const int bh_l   = (lane >> 3) & 1;

    // loader lane mapping: rows r0 = tid>>2 (0..31) and r0+32, unit au = tid&3
    const int r0l = tid >> 2, au = tid & 3;
    const int off0 = soff(r0l, au);
    const int off1 = soff(r0l + 32, au);
    const uint32_t sz0 = (r0l < rows_valid) ? 16u : 0u;
    const uint32_t sz1 = (r0l + 32 < rows_valid) ? 16u : 0u;
    const int ar0 = (r0l < rows_valid) ? r0l : 0;
    const int ar1 = (r0l + 32 < rows_valid) ? r0l + 32 : 0;

    float c[2][4][4];
#pragma unroll
    for (int a = 0; a < 2; ++a)
#pragma unroll
        for (int b = 0; b < 4; ++b)
#pragma unroll
            for (int q = 0; q < 4; ++q) c[a][b][q] = 0.f;

    int total = 0;
#pragma unroll
    for (int s = 0; s < 3; ++s) if (s < job.nseg) total += job.sg[s].K >> 5;

    int ls = 0, lch = 0;  // load cursor
    auto issue = [&](int stage) {
        const Seg sg = job.sg[ls];
        const int k0 = lch << 5;
        const uint32_t db = smem_u32(sm + stage * STAGE_BYTES);
        {
            size_t o0 = (size_t)(m0 + ar0) * sg.lda + k0 + (au << 3);
            size_t o1 = (size_t)(m0 + ar1) * sg.lda + k0 + (au << 3);
            CPASYNC(db + off0, sg.Ah + o0, sz0);
            CPASYNC(db + off1, sg.Ah + o1, sz1);
            CPASYNC(db + 4096 + off0, sg.Al + o0, sz0);
            CPASYNC(db + 4096 + off1, sg.Al + o1, sz1);
        }
        {
            size_t o0 = (size_t)(n0 + r0l) * sg.ldb + k0 + (au << 3);
            size_t o1 = (size_t)(n0 + r0l + 32) * sg.ldb + k0 + (au << 3);
            CPASYNC(db + 8192 + off0, sg.Bh + o0, 16u);
            CPASYNC(db + 8192 + off1, sg.Bh + o1, 16u);
            CPASYNC(db + 12288 + off0, sg.Bl + o0, 16u);
            CPASYNC(db + 12288 + off1, sg.Bl + o1, 16u);
        }
        if (++lch == (sg.K >> 5)) { lch = 0; ++ls; }
    };

    // prologue: 5 stages in flight (total >= 32 for all jobs here)
    issue(0); CPCOMMIT();
    issue(1); CPCOMMIT();
    issue(2); CPCOMMIT();
    issue(3); CPCOMMIT();
    issue(4); CPCOMMIT();

    int stage = 0;       // stage holding chunk t (t mod 6)
    for (int t = 0; t < total; ++t) {
        CPWAIT4();
        __syncthreads();

        const uint32_t sb = smem_u32(sm + stage * STAGE_BYTES);
        uint32_t fa[2][2][2][4];  // [ksub][hi/lo][mi][4]
        uint32_t fbr[2][2][2][4]; // [ksub][hi/lo][g][4]
#pragma unroll
        for (int ksub = 0; ksub < 2; ++ksub) {
            const int hb = ksub << 1;
#pragma unroll
            for (int mi = 0; mi < 2; ++mi) {
                uint32_t ad = sb + soff(wm * 32 + mi * 16 + arow_l, ah_l + hb);
                LDSM4(fa[ksub][0][mi], ad);
                LDSM4(fa[ksub][1][mi], ad + 4096);
            }
#pragma unroll
            for (int g = 0; g < 2; ++g) {
                uint32_t bd = sb + 8192 + soff(wn * 32 + g * 16 + brow_l, bh_l + hb);
                LDSM4(fbr[ksub][0][g], bd);
                LDSM4(fbr[ksub][1][g], bd + 4096);
            }
        }
#pragma unroll
        for (int ksub = 0; ksub < 2; ++ksub)
#pragma unroll
            for (int mi = 0; mi < 2; ++mi)
#pragma unroll
                for (int g = 0; g < 2; ++g)
#pragma unroll
                    for (int j = 0; j < 2; ++j) {
                        const int ni = g * 2 + j;
                        MMA16816(c[mi][ni], fa[ksub][0][mi],
                                 fbr[ksub][0][g][2 * j], fbr[ksub][0][g][2 * j + 1]);
                        MMA16816(c[mi][ni], fa[ksub][0][mi],
                                 fbr[ksub][1][g][2 * j], fbr[ksub][1][g][2 * j + 1]);
                        MMA16816(c[mi][ni], fa[ksub][1][mi],
                                 fbr[ksub][0][g][2 * j], fbr[ksub][0][g][2 * j + 1]);
                    }

        // issue chunk t+5 into stage (t+5)%6 == (t-1)%6 — read finished at
        // t-1; the top-of-iteration barrier above fences it for all warps.
        if (t + 5 < total) {
            int s5 = stage + 5;
            if (s5 >= NSTAGE) s5 -= NSTAGE;
            issue(s5);
        }
        CPCOMMIT();   // empty group when nothing issued — keeps accounting aligned
        if (++stage == NSTAGE) stage = 0;
    }

    // ---- epilogue ----
    if (wm * 32 < rows_valid) {
#pragma unroll
        for (int mi = 0; mi < 2; ++mi) {
            int r0 = m0 + wm * 32 + mi * 16 + (lane >> 2);
#pragma unroll
            for (int ni = 0; ni < 4; ++ni) {
                int col = n0 + wn * 32 + ni * 8 + (lane & 3) * 2;
                float v0 = c[mi][ni][0], v1 = c[mi][ni][1];
                float v2 = c[mi][ni][2], v3 = c[mi][ni][3];
                if (job.C) {
                    *(float2*)(job.C + (size_t)r0 * job.ldc + col) = make_float2(v0, v1);
                    *(float2*)(job.C + (size_t)(r0 + 8) * job.ldc + col) = make_float2(v2, v3);
                }
                if (job.Ch) {
                    __nv_bfloat162 h0 = __floats2bfloat162_rn(v0, v1);
                    __nv_bfloat162 l0 = __floats2bfloat162_rn(v0 - __low2float(h0), v1 - __high2float(h0));
                    __nv_bfloat162 h1 = __floats2bfloat162_rn(v2, v3);
                    __nv_bfloat162 l1 = __floats2bfloat162_rn(v2 - __low2float(h1), v3 - __high2float(h1));
                    *(uint32_t*)(job.Ch + (size_t)r0 * job.ldc + col) = *(uint32_t*)&h0;
                    *(uint32_t*)(job.Cl + (size_t)r0 * job.ldc + col) = *(uint32_t*)&l0;
                    *(uint32_t*)(job.Ch + (size_t)(r0 + 8) * job.ldc + col) = *(uint32_t*)&h1;
                    *(uint32_t*)(job.Cl + (size_t)(r0 + 8) * job.ldc + col) = *(uint32_t*)&l1;
                }
            }
        }
    }
}

// ---------------------------------------------------------------------------
// Conversion kernels
// ---------------------------------------------------------------------------
struct CJob { const float* s; __nv_bfloat16 *h, *l; int nblk; };
struct CJobs { CJob j[8]; };

__global__ void k_conv(CJobs js) {
    int b = blockIdx.x, ji = 0;
    while (b >= js.j[ji].nblk) { b -= js.j[ji].nblk; ++ji; }
    const CJob jb = js.j[ji];
    size_t idx = (size_t)b * 1024 + threadIdx.x * 4;
    float4 v = *(const float4*)(jb.s + idx);
    __nv_bfloat162 h0 = __floats2bfloat162_rn(v.x, v.y);
    __nv_bfloat162 h1 = __floats2bfloat162_rn(v.z, v.w);
    __nv_bfloat162 l0 = __floats2bfloat162_rn(v.x - __low2float(h0), v.y - __high2float(h0));
    __nv_bfloat162 l1 = __floats2bfloat162_rn(v.z - __low2float(h1), v.w - __high2float(h1));
    *(uint2*)(jb.h + idx) = make_uint2(*(uint32_t*)&h0, *(uint32_t*)&h1);
    *(uint2*)(jb.l + idx) = make_uint2(*(uint32_t*)&l0, *(uint32_t*)&l1);
}

__global__ void k_prep(const float* __restrict__ Wrj,
                       const float* __restrict__ Wr2s,
                       const float* __restrict__ Wr2o,
                       const float* __restrict__ rvf,
                       const float* __restrict__ vf) {
    size_t idx = (size_t)blockIdx.x * blockDim.x + threadIdx.x;
    if (idx >= BM) return;
    int n = (int)(idx >> 10), k = (int)(idx & 1023);
    const float* row = Wrj + (size_t)n * 4096;
    split1(row[k] + row[3072 + k],        g_bf + BW_W14 + idx, g_bf + BW_W14 + BM + idx);
    split1(row[1024 + k] - row[3072 + k], g_bf + BW_W24 + idx, g_bf + BW_W24 + BM + idx);
    split1(row[2048 + k],                 g_bf + BW_W3  + idx, g_bf + BW_W3  + BM + idx);
    split1(Wr2s[(size_t)k * 1024 + n],    g_bf + BW_R2ST + idx, g_bf + BW_R2ST + BM + idx);
    split1(Wr2o[(size_t)k * 1024 + n],    g_bf + BW_R2OT + idx, g_bf + BW_R2OT + BM + idx);
    split1(rvf[idx],                      g_bf + BA_RVF + idx, g_bf + BA_RVF + BM + idx);
    if (idx < NV * D) {
        float v = vf[idx];
        g_buf[O_VCX_A + idx] = v;
        split1(v, g_bf + BA_VCX0 + idx, g_bf + BA_VCX0 + K64 + idx);
        split1(v, g_bf + BA_VF + idx,   g_bf + BA_VF + K64 + idx);
    }
}

__global__ void k_elem1(const float* __restrict__ vf, const float* __restrict__ vcx,
                        const float* __restrict__ rvf, const float* __restrict__ rc) {
    int b = blockIdx.x;
    if (b < 256) {
        size_t idx = (size_t)b * 256 + threadIdx.x;
        int m = (int)(idx >> 10), d = (int)(idx & 1023);
        float a = vf[idx];
        float c = vcx[idx];
        size_t o = BA_VJCAT + (size_t)m * 4096 + d;
        split1(a,     g_bf + o,        g_bf + o + BM / 4);
        split1(c,     g_bf + o + 1024, g_bf + o + BM / 4 + 1024);
        split1(a * c, g_bf + o + 2048, g_bf + o + BM / 4 + 2048);
        split1(c - a, g_bf + o + 3072, g_bf + o + BM / 4 + 3072);
    } else {
        size_t idx = (size_t)(b - 256) * 256 + threadIdx.x;
        split1(rvf[idx] * rc[idx], g_bf + BA_RTRC + idx, g_bf + BA_RTRC + BM + idx);
    }
}

__global__ void k_rs(const int* __restrict__ eidx) {
    int e = blockIdx.x, tid = threadIdx.x;
    int ei = eidx[e];
    int i = ei >> 6, j = ei & 63;
    const float* a0 = g_buf + O_A0 + ((size_t)i << 10);
    const float* b0 = g_buf + O_B0 + ((size_t)j << 10);
    const float* cc = g_buf + O_CC + ((size_t)e << 10);
    const float* qs = g_buf + O_QS2 + ((size_t)i << 10);
    const float* qo = g_buf + O_QO2 + ((size_t)j << 10);
    float s1 = 0.f, s2 = 0.f;
#pragma unroll
    for (int c = 0; c < 4; ++c) {
        int d = tid + 256 * c;
        float r = a0[d] + b0[d] + cc[d];
        size_t o = ((size_t)e << 10) + d;
        g_buf[O_RELJ + o] = r;
        split1(r, g_bf + BA_RELJ + o, g_bf + BA_RELJ + BM + o);
        s1 += qs[d] * r;
        s2 += qo[d] * r;
    }
    __shared__ float sh[2][256];
    sh[0][tid] = s1; sh[1][tid] = s2;
    __syncthreads();
    for (int st = 128; st > 0; st >>= 1) {
        if (tid < st) { sh[0][tid] += sh[0][tid + st]; sh[1][tid] += sh[1][tid + st]; }
        __syncthreads();
    }
    if (tid == 0) {
        g_buf[O_SS + e] = sh[0][0] * 0.03125f;
        g_buf[O_SO + e] = sh[1][0] * 0.03125f;
    }
}

__global__ void k_softmax(const int* __restrict__ conn) {
    int b = blockIdx.x, lane = threadIdx.x;
    bool isRow = b < 64;
    int idx = isRow ? b : b - 64;
    int e0 = isRow ? conn[idx * 64 + lane]      : conn[lane * 64 + idx];
    int e1 = isRow ? conn[idx * 64 + lane + 32] : conn[(lane + 32) * 64 + idx];
    size_t so = isRow ? O_SS : O_SO;
    float v0 = (e0 >= 0) ? g_buf[so + e0] : -1e30f;
    float v1 = (e1 >= 0) ? g_buf[so + e1] : -1e30f;
    float m = fmaxf(v0, v1);
    for (int o = 16; o > 0; o >>= 1) m = fmaxf(m, __shfl_xor_sync(0xffffffffu, m, o));
    float x0 = (e0 >= 0) ? expf(v0 - m) : 0.f;
    float x1 = (e1 >= 0) ? expf(v1 - m) : 0.f;
    float s = x0 + x1;
    for (int o = 16; o > 0; o >>= 1) s += __shfl_xor_sync(0xffffffffu, s, o);
    float inv = 1.f / s;
    size_t wo = isRow ? O_WS : O_WO;
    if (e0 >= 0) g_buf[wo + e0] = x0 * inv;
    if (e1 >= 0) g_buf[wo + e1] = x1 * inv;
}

__global__ void k_ctx(const int* __restrict__ conn) {
    int n = blockIdx.x, tid = threadIdx.x;
    float accS[4] = {0.f, 0.f, 0.f, 0.f};
    float accO[4] = {0.f, 0.f, 0.f, 0.f};
    for (int p = 0; p < 64; ++p) {
        int eS = conn[n * 64 + p];
        if (eS >= 0) {
            float w = g_buf[O_WS + eS];
            const float* r = g_buf + O_RELJ + ((size_t)eS << 10);
#pragma unroll
            for (int c = 0; c < 4; ++c) accS[c] += w * r[tid + 256 * c];
        }
        int eO = conn[p * 64 + n];
        if (eO >= 0) {
            float w = g_buf[O_WO + eO];
            const float* r = g_buf + O_RELJ + ((size_t)eO << 10);
#pragma unroll
            for (int c = 0; c < 4; ++c) accO[c] += w * r[tid + 256 * c];
        }
    }
#pragma unroll
    for (int c = 0; c < 4; ++c) {
        size_t o = ((size_t)n << 10) + tid + 256 * c;
        split1(accS[c], g_bf + BA_CTXS + o, g_bf + BA_CTXS + K64 + o);
        split1(accO[c], g_bf + BA_CTXO + o, g_bf + BA_CTXO + K64 + o);
    }
}

__global__ void k_voutepi(const int* __restrict__ conn,
                          const float* __restrict__ bnode,
                          const float* __restrict__ vf,
                          float* __restrict__ vout) {
    int i = blockIdx.x, tid = threadIdx.x;
    __shared__ int s_deg;
    if (tid == 0) {
        int dc = 0;
        for (int p = 0; p < 64; ++p)
            dc += (conn[i * 64 + p] >= 0) + (conn[p * 64 + i] >= 0);
        s_deg = dc;
    }
    __syncthreads();
    for (int d = tid; d < 1024; d += 256) {
        float v = vout[((size_t)i << 10) + d] + bnode[d];
        if (s_deg == 0) v = vf[((size_t)i << 10) + d];
        vout[((size_t)i << 10) + d] = v;
    }
}

// ---------------------------------------------------------------------------
extern "C" void kernel_launch(void* const* d_in, const int* in_sizes, int n_in,
                              void* d_out, int out_size) {
    (void)in_sizes; (void)n_in; (void)out_size;
    const float* vf     = (const float*)d_in[0];
    const float* rvf    = (const float*)d_in[1];
    const int*   conn   = (const int*)d_in[2];
    const int*   eidx   = (const int*)d_in[4];
    const float* W_sub  = (const float*)d_in[5];
    const float* W_obj  = (const float*)d_in[6];
    const float* W_joint= (const float*)d_in[9];
    const float* W_ctx  = (const float*)d_in[10];
    const float* W_ru   = (const float*)d_in[11];
    const float* W_rj   = (const float*)d_in[12];
    const float* W_rc   = (const float*)d_in[13];
    const float* W_node = (const float*)d_in[14];
    const float* b_node = (const float*)d_in[15];
    const float* W_fac  = (const float*)d_in[16];
    float* out = (float*)d_out;

    cudaFuncSetAttribute(tc_gemm, cudaFuncAttributeMaxDynamicSharedMemorySize, SMEM_BYTES);

    float* fb = nullptr;
    __nv_bfloat16* bb = nullptr;
    cudaGetSymbolAddress((void**)&fb, g_buf);
    cudaGetSymbolAddress((void**)&bb, g_bf);

    auto seg = [&](size_t a, size_t asz, size_t b, size_t bsz, int lda, int ldb, int K) {
        return Seg{bb + a, bb + a + asz, bb + b, bb + b + bsz, lda, ldb, K};
    };
    auto segW = [&](size_t a, size_t asz, size_t wb, size_t wsz, size_t wcol,
                    int lda, int ldb, int K) {
        return Seg{bb + a, bb + a + asz, bb + wb + wcol, bb + wb + wsz + wcol, lda, ldb, K};
    };

    {
        CJobs cj{};
        cj.j[0] = CJob{W_joint, bb + BW_JOINT, bb + BW_JOINT + 4 * BM, 4096};
        cj.j[1] = CJob{W_ru,    bb + BW_RU,    bb + BW_RU    + 3 * BM, 3072};
        cj.j[2] = CJob{W_sub,   bb + BW_SUB,   bb + BW_SUB   + BM,     1024};
        cj.j[3] = CJob{W_obj,   bb + BW_OBJ,   bb + BW_OBJ   + BM,     1024};
        cj.j[4] = CJob{W_ctx,   bb + BW_CTX,   bb + BW_CTX   + 3 * BM, 3072};
        cj.j[5] = CJob{W_rc,    bb + BW_RC,    bb + BW_RC    + 2 * BM, 2048};
        cj.j[6] = CJob{W_node,  bb + BW_NODE,  bb + BW_NODE  + 2 * BM, 2048};
        cj.j[7] = CJob{W_fac,   bb + BW_FAC,   bb + BW_FAC   + 2 * BM, 2048};
        k_conv<<<18432, 256>>>(cj);
    }
    k_prep<<<4096, 256>>>(W_rj, (const float*)d_in[7], (const float*)d_in[8], rvf, vf);

    for (int t = 0; t < 2; ++t) {
        const size_t rcP   = (t == 0) ? BA_RVF : BA_RC0;
        const float* rcF   = (t == 0) ? rvf : fb + O_RCF;
        const float* vcxF  = (t == 0) ? fb + O_VCX_A : fb + O_VCX_B;
        const size_t vcxP  = (t == 0) ? BA_VCX0 : BA_VCX1;

        k_elem1<<<4352, 256>>>(vf, vcxF, rvf, rcF);

        // Launch A: vj (M=64) + rj (M=1024, 3 segs)
        {
            Batch bt{};
            Job j0{};
            j0.sg[0] = seg(BA_VJCAT, BM / 4, BW_JOINT, 4 * BM, 4096, 4096, 4096);
            j0.nseg = 1; j0.C = nullptr; j0.Ch = bb + BA_VJ; j0.Cl = bb + BA_VJ + K64;
            j0.ldc = 1024; j0.M = 64; j0.mtiles = 1;
            bt.j[0] = j0;
            Job j1{};
            j1.sg[0] = seg(BA_RVF, BM, BW_W14, BM, 1024, 1024, 1024);
            j1.sg[1] = seg(rcP,    BM, BW_W24, BM, 1024, 1024, 1024);
            j1.sg[2] = seg(BA_RTRC, BM, BW_W3, BM, 1024, 1024, 1024);
            j1.nseg = 3; j1.C = nullptr; j1.Ch = bb + BA_RJ; j1.Cl = bb + BA_RJ + BM;
            j1.ldc = 1024; j1.M = 1024; j1.mtiles = 16;
            bt.j[1] = j1;
            tc_gemm<<<dim3(16, 16, 2), 128, SMEM_BYTES>>>(bt);
        }

        // Launch B: cc + A0,B0 + QS,QO
        {
            Batch bt{};
            Job j0{};
            j0.sg[0] = segW(BA_RJ, BM, BW_RU, 3 * BM, 2048, 1024, 3072, 1024);
            j0.nseg = 1; j0.C = fb + O_CC; j0.Ch = nullptr; j0.Cl = nullptr;
            j0.ldc = 1024; j0.M = 1024; j0.mtiles = 16;
            bt.j[0] = j0;
            Job j1{};
            j1.sg[0] = segW(BA_VJ, K64, BW_RU, 3 * BM, 0, 1024, 3072, 1024);
            j1.nseg = 1; j1.C = fb + O_A0; j1.ldc = 1024; j1.M = 64; j1.mtiles = 1;
            bt.j[1] = j1;
            Job j2 = j1;
            j2.sg[0] = segW(BA_VJ, K64, BW_RU, 3 * BM, 1024, 1024, 3072, 1024);
            j2.C = fb + O_B0;
            bt.j[2] = j2;
            Job j3{};
            j3.sg[0] = seg(BA_VJ, K64, BW_SUB, BM, 1024, 1024, 1024);
            j3.nseg = 1; j3.C = nullptr; j3.Ch = bb + BA_QS; j3.Cl = bb + BA_QS + K64;
            j3.ldc = 1024; j3.M = 64; j3.mtiles = 1;
            bt.j[3] = j3;
            Job j4 = j3;
            j4.sg[0] = seg(BA_VJ, K64, BW_OBJ, BM, 1024, 1024, 1024);
            j4.Ch = bb + BA_QO; j4.Cl = bb + BA_QO + K64;
            bt.j[4] = j4;
            tc_gemm<<<dim3(16, 16, 5), 128, SMEM_BYTES>>>(bt);
        }

        // Launch C: qs2, qo2
        {
            Batch bt{};
            Job j0{};
            j0.sg[0] = seg(BA_QS, K64, BW_R2ST, BM, 1024, 1024, 1024);
            j0.nseg = 1; j0.C = fb + O_QS2; j0.ldc = 1024; j0.M = 64; j0.mtiles = 1;
            bt.j[0] = j0;
            Job j1 = j0;
            j1.sg[0] = seg(BA_QO, K64, BW_R2OT, BM, 1024, 1024, 1024);
            j1.C = fb + O_QO2;
            bt.j[1] = j1;
            tc_gemm<<<dim3(16, 1, 2), 128, SMEM_BYTES>>>(bt);
        }

        k_rs<<<1024, 256>>>(eidx);
        k_softmax<<<128, 32>>>(conn);
        k_ctx<<<64, 256>>>(conn);

        // Launch D: vctx' + rc'
        {
            Batch bt{};
            Job jv{};
            jv.sg[0] = segW(vcxP,    K64, BW_CTX, 3 * BM, 0,    1024, 3072, 1024);
            jv.sg[1] = segW(BA_CTXS, K64, BW_CTX, 3 * BM, 1024, 1024, 3072, 1024);
            jv.sg[2] = segW(BA_CTXO, K64, BW_CTX, 3 * BM, 2048, 1024, 3072, 1024);
            jv.nseg = 3; jv.ldc = 1024; jv.M = 64; jv.mtiles = 1;
            if (t == 0) {
                jv.C = fb + O_VCX_B;
                jv.Ch = bb + BA_VCX1; jv.Cl = bb + BA_VCX1 + K64;
            } else {
                jv.C = nullptr;
                jv.Ch = bb + BA_VCX0; jv.Cl = bb + BA_VCX0 + K64;
            }
            bt.j[0] = jv;
            Job jr{};
            jr.sg[0] = segW(rcP,     BM, BW_RC, 2 * BM, 0,    1024, 2048, 1024);
            jr.sg[1] = segW(BA_RELJ, BM, BW_RC, 2 * BM, 1024, 1024, 2048, 1024);
            jr.nseg = 2; jr.ldc = 1024; jr.M = 1024; jr.mtiles = 16;
            if (t == 0) {
                jr.C = fb + O_RCF;
                jr.Ch = bb + BA_RC0; jr.Cl = bb + BA_RC0 + BM;
            } else {
                jr.C = nullptr;
                jr.Ch = bb + BA_RC1; jr.Cl = bb + BA_RC1 + BM;
            }
            bt.j[1] = jr;
            tc_gemm<<<dim3(16, 16, 2), 128, SMEM_BYTES>>>(bt);
        }
    }

    // Final: rel_out + v_out
    float* vout = out + (size_t)NE * D;
    {
        Batch bt{};
        Job jr{};
        jr.sg[0] = segW(BA_RVF, BM, BW_FAC, 2 * BM, 0,    1024, 2048, 1024);
        jr.sg[1] = segW(BA_RC1, BM, BW_FAC, 2 * BM, 1024, 1024, 2048, 1024);
        jr.nseg = 2; jr.C = out; jr.ldc = 1024; jr.M = 1024; jr.mtiles = 16;
        bt.j[0] = jr;
        Job jv{};
        jv.sg[0] = segW(BA_VF,   K64, BW_NODE, 2 * BM, 0,    1024, 2048, 1024);
        jv.sg[1] = segW(BA_VCX0, K64, BW_NODE, 2 * BM, 1024, 1024, 2048, 1024);
        jv.nseg = 2; jv.C = vout; jv.ldc = 1024; jv.M = 64; jv.mtiles = 1;
        bt.j[1] = jv;
        tc_gemm<<<dim3(16, 16, 2), 128, SMEM_BYTES>>>(bt);
    }
    k_voutepi<<<64, 256>>>(conn, b_node, vf, vout);
}